// round 1
// baseline (speedup 1.0000x reference)
#include <cuda_runtime.h>
#include <math.h>
#include <stdint.h>

// Problem dims
constexpr int kB  = 4;
constexpr int kT  = 2048;
constexpr int kD  = 1024;
constexpr int kH  = 16;
constexpr int kDH = 64;
constexpr int kBT = kB * kT;           // 8192
constexpr int kQKVN = 3 * kD;          // 3072

// Scratch (static device globals: allocation-free per harness rules)
__device__ float g_qkv[(size_t)kBT * kQKVN];   // 96 MB
__device__ float g_q[(size_t)kBT * kD];        // 32 MB  [bh][t][d]
__device__ float g_k[(size_t)kBT * kD];
__device__ float g_v[(size_t)kBT * kD];
__device__ float g_att[(size_t)kBT * kD];      // 32 MB  [bt][h*64+d]

// ---------------------------------------------------------------------------
// Generic fp32 SGEMM body: C[M,N] = A[M,K] @ B[K,N], all row-major.
// 128x128 block tile, BK=16, 256 threads, 8x8 per-thread microtile.
// ---------------------------------------------------------------------------
__device__ __forceinline__ void sgemm_body(
    const float* __restrict__ A, const float* __restrict__ Bm,
    float* __restrict__ C, int M, int N, int K)
{
    __shared__ float As[16][128];   // transposed: As[k][m]
    __shared__ float Bs[16][128];   // Bs[k][n]

    const int tid  = threadIdx.x;
    const int brow = blockIdx.y;
    const int bcol = blockIdx.x;
    const int tRow = (tid >> 4) << 3;   // 0..120
    const int tCol = (tid & 15) << 3;

    float acc[8][8];
    #pragma unroll
    for (int i = 0; i < 8; i++)
        #pragma unroll
        for (int j = 0; j < 8; j++) acc[i][j] = 0.f;

    const float* Ap = A + (size_t)brow * 128 * K;
    const float* Bp = Bm + (size_t)bcol * 128;

    for (int k0 = 0; k0 < K; k0 += 16) {
        #pragma unroll
        for (int u = 0; u < 2; u++) {
            int idx = tid + u * 256;
            int aR = idx >> 2;              // 0..127
            int aC = (idx & 3) << 2;        // 0,4,8,12
            float4 av = *(const float4*)(Ap + (size_t)aR * K + k0 + aC);
            As[aC + 0][aR] = av.x;
            As[aC + 1][aR] = av.y;
            As[aC + 2][aR] = av.z;
            As[aC + 3][aR] = av.w;
            int bR = idx >> 5;              // 0..15
            int bC = (idx & 31) << 2;       // 0..124
            *(float4*)&Bs[bR][bC] =
                *(const float4*)(Bp + (size_t)(k0 + bR) * N + bC);
        }
        __syncthreads();

        #pragma unroll
        for (int kk = 0; kk < 16; kk++) {
            float ar[8], br[8];
            *(float4*)&ar[0] = *(const float4*)&As[kk][tRow];
            *(float4*)&ar[4] = *(const float4*)&As[kk][tRow + 4];
            *(float4*)&br[0] = *(const float4*)&Bs[kk][tCol];
            *(float4*)&br[4] = *(const float4*)&Bs[kk][tCol + 4];
            #pragma unroll
            for (int i = 0; i < 8; i++)
                #pragma unroll
                for (int j = 0; j < 8; j++)
                    acc[i][j] += ar[i] * br[j];
        }
        __syncthreads();
    }

    #pragma unroll
    for (int i = 0; i < 8; i++) {
        float* Cp = C + (size_t)(brow * 128 + tRow + i) * N + bcol * 128 + tCol;
        *(float4*)Cp       = make_float4(acc[i][0], acc[i][1], acc[i][2], acc[i][3]);
        *(float4*)(Cp + 4) = make_float4(acc[i][4], acc[i][5], acc[i][6], acc[i][7]);
    }
}

__global__ __launch_bounds__(256)
void gemm_qkv_kernel(const float* __restrict__ x, const float* __restrict__ Wqkv)
{
    sgemm_body(x, Wqkv, g_qkv, kBT, kQKVN, kD);
}

__global__ __launch_bounds__(256)
void gemm_out_kernel(const float* __restrict__ Wout, float* __restrict__ out)
{
    sgemm_body(g_att, Wout, out, kBT, kD, kD);
}

// ---------------------------------------------------------------------------
// RoPE + split/transpose: g_qkv[bt, {q|k|v}*1024 + h*64 + d]
//   -> g_q/g_k (roped), g_v, each laid out [bh][t][64]
// One thread per (bt, h, i) with i in [0,32): handles the (i, i+32) pair.
// ---------------------------------------------------------------------------
__global__ __launch_bounds__(256)
void rope_kernel()
{
    int idx = blockIdx.x * blockDim.x + threadIdx.x;
    if (idx >= kBT * kH * 32) return;
    int i  = idx & 31;
    int h  = (idx >> 5) & (kH - 1);
    int bt = idx >> 9;
    int t  = bt & (kT - 1);
    int b  = bt >> 11;

    // inv_freq[i] = 10000^(-(2i)/64)
    float inv_freq = expf(-((float)(2 * i) / 64.0f) * 9.210340371976184f);
    float ang = (float)t * inv_freq;
    float s, c;
    sincosf(ang, &s, &c);

    size_t src = (size_t)bt * kQKVN + h * kDH + i;
    float q1 = g_qkv[src],        q2 = g_qkv[src + 32];
    float k1 = g_qkv[src + 1024], k2 = g_qkv[src + 1056];
    float v1 = g_qkv[src + 2048], v2 = g_qkv[src + 2080];

    size_t dst = ((size_t)(b * kH + h) * kT + t) * kDH + i;
    g_q[dst]      = q1 * c - q2 * s;
    g_q[dst + 32] = q2 * c + q1 * s;
    g_k[dst]      = k1 * c - k2 * s;
    g_k[dst + 32] = k2 * c + k1 * s;
    g_v[dst]      = v1;
    g_v[dst + 32] = v2;
}

// ---------------------------------------------------------------------------
// Flash-style causal attention. grid = (T/64, B*H), 256 threads.
// Thread (row = tid/4, cg = tid%4) owns score cols / out dims cg*16..cg*16+15.
// smem layouts chosen so all hot loads are broadcast-scalar or same-row float4.
// ---------------------------------------------------------------------------
__global__ __launch_bounds__(256)
void attn_kernel()
{
    __shared__ float sQT[64 * 64];  // [d][row], pre-scaled by 1/8
    __shared__ float sKV[64 * 64];  // K phase: [d][kc]; V phase: [kc][d]
    __shared__ float sPT[64 * 64];  // [kc][row]

    const int qt  = blockIdx.x;
    const int bh  = blockIdx.y;
    const int b   = bh >> 4;
    const int h   = bh & 15;
    const int tid = threadIdx.x;
    const int row = tid >> 2;
    const int cg  = tid & 3;

    const float* Qb = g_q + ((size_t)bh * kT + qt * 64) * kDH;
    const float* Kb = g_k + (size_t)bh * kT * kDH;
    const float* Vb = g_v + (size_t)bh * kT * kDH;

    // Load Q tile transposed, fold in softmax scale 1/sqrt(64)
    for (int i = tid; i < 1024; i += 256) {
        int r  = i >> 4;
        int d4 = (i & 15) << 2;
        float4 qv = *(const float4*)(Qb + (size_t)r * kDH + d4);
        sQT[(d4 + 0) * 64 + r] = qv.x * 0.125f;
        sQT[(d4 + 1) * 64 + r] = qv.y * 0.125f;
        sQT[(d4 + 2) * 64 + r] = qv.z * 0.125f;
        sQT[(d4 + 3) * 64 + r] = qv.w * 0.125f;
    }

    float m = -1e30f, l = 0.f;
    float o[16];
    #pragma unroll
    for (int i = 0; i < 16; i++) o[i] = 0.f;

    for (int kt = 0; kt <= qt; kt++) {
        __syncthreads();   // protect sKV (prev V) and sPT (prev P) reuse
        // Load K tile transposed: sKV[d][kc]
        for (int i = tid; i < 1024; i += 256) {
            int r  = i >> 4;
            int d4 = (i & 15) << 2;
            float4 kv = *(const float4*)(Kb + ((size_t)(kt * 64 + r)) * kDH + d4);
            sKV[(d4 + 0) * 64 + r] = kv.x;
            sKV[(d4 + 1) * 64 + r] = kv.y;
            sKV[(d4 + 2) * 64 + r] = kv.z;
            sKV[(d4 + 3) * 64 + r] = kv.w;
        }
        __syncthreads();

        // Scores: s[j] = (Q[row]/8) . K[cg*16+j]
        float s[16];
        #pragma unroll
        for (int j = 0; j < 16; j++) s[j] = 0.f;
        #pragma unroll 8
        for (int d = 0; d < 64; d++) {
            float qv = sQT[d * 64 + row];
            const float4* kp = (const float4*)&sKV[d * 64 + (cg << 4)];
            float4 ka = kp[0], kb2 = kp[1], kc2 = kp[2], kd2 = kp[3];
            s[0]  += qv * ka.x;  s[1]  += qv * ka.y;  s[2]  += qv * ka.z;  s[3]  += qv * ka.w;
            s[4]  += qv * kb2.x; s[5]  += qv * kb2.y; s[6]  += qv * kb2.z; s[7]  += qv * kb2.w;
            s[8]  += qv * kc2.x; s[9]  += qv * kc2.y; s[10] += qv * kc2.z; s[11] += qv * kc2.w;
            s[12] += qv * kd2.x; s[13] += qv * kd2.y; s[14] += qv * kd2.z; s[15] += qv * kd2.w;
        }

        if (kt == qt) {
            #pragma unroll
            for (int j = 0; j < 16; j++)
                if ((cg << 4) + j > row) s[j] = -1e30f;
        }

        // Online softmax; row stats live redundantly in the 4 lanes of each row
        float tmax = s[0];
        #pragma unroll
        for (int j = 1; j < 16; j++) tmax = fmaxf(tmax, s[j]);
        tmax = fmaxf(tmax, __shfl_xor_sync(0xffffffffu, tmax, 1));
        tmax = fmaxf(tmax, __shfl_xor_sync(0xffffffffu, tmax, 2));
        float mnew = fmaxf(m, tmax);
        float corr = __expf(m - mnew);
        float psum = 0.f;
        #pragma unroll
        for (int j = 0; j < 16; j++) {
            s[j] = __expf(s[j] - mnew);
            psum += s[j];
        }
        psum += __shfl_xor_sync(0xffffffffu, psum, 1);
        psum += __shfl_xor_sync(0xffffffffu, psum, 2);
        l = l * corr + psum;
        m = mnew;
        #pragma unroll
        for (int i = 0; i < 16; i++) o[i] *= corr;

        // Stash P transposed: sPT[kc][row]
        #pragma unroll
        for (int j = 0; j < 16; j++)
            sPT[((cg << 4) + j) * 64 + row] = s[j];
        __syncthreads();

        // Load V tile natural layout into sKV: [kc][d]
        for (int i = tid; i < 1024; i += 256) {
            int r  = i >> 4;
            int d4 = (i & 15) << 2;
            *(float4*)&sKV[r * 64 + d4] =
                *(const float4*)(Vb + ((size_t)(kt * 64 + r)) * kDH + d4);
        }
        __syncthreads();

        // O += P @ V
        #pragma unroll 8
        for (int kk = 0; kk < 64; kk++) {
            float pv = sPT[kk * 64 + row];
            const float4* vp = (const float4*)&sKV[kk * 64 + (cg << 4)];
            float4 va = vp[0], vb2 = vp[1], vc2 = vp[2], vd2 = vp[3];
            o[0]  += pv * va.x;  o[1]  += pv * va.y;  o[2]  += pv * va.z;  o[3]  += pv * va.w;
            o[4]  += pv * vb2.x; o[5]  += pv * vb2.y; o[6]  += pv * vb2.z; o[7]  += pv * vb2.w;
            o[8]  += pv * vc2.x; o[9]  += pv * vc2.y; o[10] += pv * vc2.z; o[11] += pv * vc2.w;
            o[12] += pv * vd2.x; o[13] += pv * vd2.y; o[14] += pv * vd2.z; o[15] += pv * vd2.w;
        }
    }

    // Epilogue: normalize, write [bt][h*64+d] so GEMM2 consumes row-major
    float linv = 1.f / l;
    size_t obase = ((size_t)(b * kT + qt * 64 + row)) * kD + h * kDH + (cg << 4);
    *(float4*)&g_att[obase + 0]  = make_float4(o[0]*linv,  o[1]*linv,  o[2]*linv,  o[3]*linv);
    *(float4*)&g_att[obase + 4]  = make_float4(o[4]*linv,  o[5]*linv,  o[6]*linv,  o[7]*linv);
    *(float4*)&g_att[obase + 8]  = make_float4(o[8]*linv,  o[9]*linv,  o[10]*linv, o[11]*linv);
    *(float4*)&g_att[obase + 12] = make_float4(o[12]*linv, o[13]*linv, o[14]*linv, o[15]*linv);
}

// ---------------------------------------------------------------------------
extern "C" void kernel_launch(void* const* d_in, const int* in_sizes, int n_in,
                              void* d_out, int out_size)
{
    const float* x    = (const float*)d_in[0];
    const float* Wqkv = (const float*)d_in[1];
    const float* Wout = (const float*)d_in[2];
    float* out        = (float*)d_out;

    dim3 blk(256);
    // 1) QKV projection: [8192,1024] @ [1024,3072]
    gemm_qkv_kernel<<<dim3(kQKVN / 128, kBT / 128), blk>>>(x, Wqkv);
    // 2) RoPE + head split/transpose
    int rope_threads = kBT * kH * 32;
    rope_kernel<<<(rope_threads + 255) / 256, blk>>>();
    // 3) Causal flash attention
    attn_kernel<<<dim3(kT / 64, kB * kH), blk>>>();
    // 4) Output projection: [8192,1024] @ [1024,1024]
    gemm_out_kernel<<<dim3(kD / 128, kBT / 128), blk>>>(Wout, out);
}

// round 3
// speedup vs baseline: 7.0750x; 7.0750x over previous
#include <cuda_runtime.h>
#include <math.h>
#include <stdint.h>

// Problem dims
constexpr int kB  = 4;
constexpr int kT  = 2048;
constexpr int kD  = 1024;
constexpr int kH  = 16;
constexpr int kDH = 64;
constexpr int kBT = kB * kT;           // 8192
constexpr int kQKVN = 3 * kD;          // 3072

// Scratch
__device__ float g_qkv[(size_t)kBT * kQKVN];     // 96 MB
__device__ float g_q[(size_t)kBT * kD];          // [bh][t][64], tf32-rounded
__device__ float g_k[(size_t)kBT * kD];
__device__ float g_v[(size_t)kBT * kD];
__device__ float g_att[(size_t)kBT * kD];        // [bt][h*64+d], tf32-rounded
__device__ float g_xr[(size_t)kBT * kD];         // tf32-rounded copies
__device__ float g_wqkvr[(size_t)kD * kQKVN];
__device__ float g_woutr[(size_t)kD * kD];

// ---------------------------------------------------------------------------
__device__ __forceinline__ float to_tf32(float x) {
    uint32_t r;
    asm("cvt.rna.tf32.f32 %0, %1;" : "=r"(r) : "f"(x));
    return __uint_as_float(r);
}
__device__ __forceinline__ uint32_t f2b(float x) { return __float_as_uint(x); }

__device__ __forceinline__ void mma8(float& d0, float& d1, float& d2, float& d3,
                                     uint32_t a0, uint32_t a1, uint32_t a2, uint32_t a3,
                                     uint32_t b0, uint32_t b1) {
    asm volatile(
        "mma.sync.aligned.m16n8k8.row.col.f32.tf32.tf32.f32 "
        "{%0,%1,%2,%3}, {%4,%5,%6,%7}, {%8,%9}, {%0,%1,%2,%3};\n"
        : "+f"(d0), "+f"(d1), "+f"(d2), "+f"(d3)
        : "r"(a0), "r"(a1), "r"(a2), "r"(a3), "r"(b0), "r"(b1));
}

__device__ __forceinline__ void cpa16(void* s, const void* g) {
    uint32_t sa = (uint32_t)__cvta_generic_to_shared(s);
    asm volatile("cp.async.cg.shared.global [%0], [%1], 16;\n" :: "r"(sa), "l"(g));
}
__device__ __forceinline__ void cpa_commit() {
    asm volatile("cp.async.commit_group;\n");
}

// ---------------------------------------------------------------------------
__global__ __launch_bounds__(256)
void round_tf32_kernel(const float* __restrict__ in, float* __restrict__ out, int n4)
{
    int i = blockIdx.x * blockDim.x + threadIdx.x;
    if (i >= n4) return;
    float4 v = ((const float4*)in)[i];
    v.x = to_tf32(v.x); v.y = to_tf32(v.y); v.z = to_tf32(v.z); v.w = to_tf32(v.w);
    ((float4*)out)[i] = v;
}

// ---------------------------------------------------------------------------
// tf32 GEMM: C[M,N] = A[M,K] @ B[K,N], row-major, A/B pre-rounded to tf32.
// 128x128 tile, BK=16, 256 threads, 8 warps (2x4), warp tile 64x32.
// ---------------------------------------------------------------------------
__global__ __launch_bounds__(256)
void gemm_tf32_kernel(const float* __restrict__ A, const float* __restrict__ B,
                      float* __restrict__ C, int M, int N, int K)
{
    __shared__ float As[2][128][20];   // rows padded to 20 floats
    __shared__ float Bs[2][16][136];   // rows padded to 136 floats

    const int tid  = threadIdx.x;
    const int lane = tid & 31, warp = tid >> 5;
    const int wm = (warp >> 2) * 64, wn = (warp & 3) * 32;
    const int g = lane >> 2, tg = lane & 3;
    const int brow = blockIdx.y * 128, bcol = blockIdx.x * 128;

    float acc[4][4][4];
    #pragma unroll
    for (int a = 0; a < 4; a++)
        #pragma unroll
        for (int b = 0; b < 4; b++)
            #pragma unroll
            for (int c = 0; c < 4; c++) acc[a][b][c] = 0.f;

    const int iters = K >> 4;

    // stage 0 loads
    {
        #pragma unroll
        for (int u = 0; u < 2; u++) {
            int idx = tid + u * 256;
            int r = idx >> 2, c = (idx & 3) << 2;
            cpa16(&As[0][r][c], A + (size_t)(brow + r) * K + c);
            int br = idx >> 5, bc = (idx & 31) << 2;
            cpa16(&Bs[0][br][bc], B + (size_t)br * N + bcol + bc);
        }
        cpa_commit();
    }

    for (int it = 0; it < iters; it++) {
        if (it + 1 < iters) {
            int k0 = (it + 1) << 4;
            int nb = (it + 1) & 1;
            #pragma unroll
            for (int u = 0; u < 2; u++) {
                int idx = tid + u * 256;
                int r = idx >> 2, c = (idx & 3) << 2;
                cpa16(&As[nb][r][c], A + (size_t)(brow + r) * K + k0 + c);
                int br = idx >> 5, bc = (idx & 31) << 2;
                cpa16(&Bs[nb][br][bc], B + (size_t)(k0 + br) * N + bcol + bc);
            }
            cpa_commit();
            asm volatile("cp.async.wait_group 1;\n");
        } else {
            asm volatile("cp.async.wait_group 0;\n");
        }
        __syncthreads();
        const int buf = it & 1;

        #pragma unroll
        for (int ks = 0; ks < 16; ks += 8) {
            uint32_t a[4][4];
            #pragma unroll
            for (int mt = 0; mt < 4; mt++) {
                int r = wm + mt * 16;
                a[mt][0] = f2b(As[buf][r + g][ks + tg]);
                a[mt][1] = f2b(As[buf][r + g + 8][ks + tg]);
                a[mt][2] = f2b(As[buf][r + g][ks + tg + 4]);
                a[mt][3] = f2b(As[buf][r + g + 8][ks + tg + 4]);
            }
            #pragma unroll
            for (int nt = 0; nt < 4; nt++) {
                int n0 = wn + nt * 8;
                uint32_t b0 = f2b(Bs[buf][ks + tg][n0 + g]);
                uint32_t b1 = f2b(Bs[buf][ks + tg + 4][n0 + g]);
                #pragma unroll
                for (int mt = 0; mt < 4; mt++)
                    mma8(acc[mt][nt][0], acc[mt][nt][1], acc[mt][nt][2], acc[mt][nt][3],
                         a[mt][0], a[mt][1], a[mt][2], a[mt][3], b0, b1);
            }
        }
        __syncthreads();
    }

    #pragma unroll
    for (int mt = 0; mt < 4; mt++) {
        #pragma unroll
        for (int nt = 0; nt < 4; nt++) {
            int r0 = brow + wm + mt * 16 + g;
            int c0 = bcol + wn + nt * 8 + 2 * tg;
            *(float2*)&C[(size_t)r0 * N + c0]       = make_float2(acc[mt][nt][0], acc[mt][nt][1]);
            *(float2*)&C[(size_t)(r0 + 8) * N + c0] = make_float2(acc[mt][nt][2], acc[mt][nt][3]);
        }
    }
}

// ---------------------------------------------------------------------------
// RoPE + split/transpose + tf32 rounding
// ---------------------------------------------------------------------------
__global__ __launch_bounds__(256)
void rope_kernel()
{
    int idx = blockIdx.x * blockDim.x + threadIdx.x;
    if (idx >= kBT * kH * 32) return;
    int i  = idx & 31;
    int h  = (idx >> 5) & (kH - 1);
    int bt = idx >> 9;
    int t  = bt & (kT - 1);
    int b  = bt >> 11;

    float inv_freq = expf(-((float)(2 * i) / 64.0f) * 9.210340371976184f);
    float ang = (float)t * inv_freq;
    float s, c;
    sincosf(ang, &s, &c);

    size_t src = (size_t)bt * kQKVN + h * kDH + i;
    float q1 = g_qkv[src],        q2 = g_qkv[src + 32];
    float k1 = g_qkv[src + 1024], k2 = g_qkv[src + 1056];
    float v1 = g_qkv[src + 2048], v2 = g_qkv[src + 2080];

    size_t dst = ((size_t)(b * kH + h) * kT + t) * kDH + i;
    g_q[dst]      = to_tf32(q1 * c - q2 * s);
    g_q[dst + 32] = to_tf32(q2 * c + q1 * s);
    g_k[dst]      = to_tf32(k1 * c - k2 * s);
    g_k[dst + 32] = to_tf32(k2 * c + k1 * s);
    g_v[dst]      = to_tf32(v1);
    g_v[dst + 32] = to_tf32(v2);
}

// ---------------------------------------------------------------------------
// Flash attention, tf32 mma. CTA = 128 q rows, 4 warps (32 rows each),
// 64-key tiles, cp.async double-buffered K/V, P via smem.
// smem (floats): sQ[128][68] | sP[128][68] | sK[2][64][68] | sV[2][64][72]
// ---------------------------------------------------------------------------
constexpr int ATT_SMEM_FLOATS = 8704 + 8704 + 2 * 4352 + 2 * 4608;  // 35328
constexpr int ATT_SMEM_BYTES  = ATT_SMEM_FLOATS * 4;                 // 141312

__global__ __launch_bounds__(128)
void attn_tf32_kernel()
{
    extern __shared__ float sm[];
    float* sQ = sm;                       // [128][68]
    float* sP = sm + 8704;                // [128][68]
    float* sK = sm + 17408;               // [2][64][68]
    float* sV = sm + 17408 + 2 * 4352;    // [2][64][72]

    const int qt = blockIdx.x;            // 0..15 (128-row tiles)
    const int bh = blockIdx.y;
    const int b  = bh >> 4, h = bh & 15;
    const int tid = threadIdx.x, lane = tid & 31, warp = tid >> 5;
    const int g = lane >> 2, tg = lane & 3;
    const int m0 = warp * 32;

    const float* Qg = g_q + ((size_t)bh * kT + qt * 128) * kDH;
    const float* Kg = g_k + (size_t)bh * kT * kDH;
    const float* Vg = g_v + (size_t)bh * kT * kDH;

    // Load Q tile (scale by 1/8 — exact power of 2, stays tf32)
    for (int i = tid; i < 2048; i += 128) {
        int r = i >> 4, c = (i & 15) << 2;
        float4 v = *(const float4*)(Qg + r * 64 + c);
        v.x *= 0.125f; v.y *= 0.125f; v.z *= 0.125f; v.w *= 0.125f;
        *(float4*)&sQ[r * 68 + c] = v;
    }

    float o[2][8][4];
    #pragma unroll
    for (int mt = 0; mt < 2; mt++)
        #pragma unroll
        for (int nt = 0; nt < 8; nt++)
            #pragma unroll
            for (int e = 0; e < 4; e++) o[mt][nt][e] = 0.f;
    float mrow[4] = {-1e30f, -1e30f, -1e30f, -1e30f};
    float lrow[4] = {0.f, 0.f, 0.f, 0.f};

    const int nkt = 2 * qt + 2;

    // prologue: stage kt=0
    for (int i = tid; i < 1024; i += 128) {
        int r = i >> 4, c = (i & 15) << 2;
        cpa16(&sK[r * 68 + c], Kg + (size_t)r * 64 + c);
        cpa16(&sV[r * 72 + c], Vg + (size_t)r * 64 + c);
    }
    cpa_commit();

    for (int kt = 0; kt < nkt; kt++) {
        if (kt + 1 < nkt) {
            int nb = (kt + 1) & 1;
            const float* Kn = Kg + (size_t)(kt + 1) * 64 * 64;
            const float* Vn = Vg + (size_t)(kt + 1) * 64 * 64;
            for (int i = tid; i < 1024; i += 128) {
                int r = i >> 4, c = (i & 15) << 2;
                cpa16(&sK[nb * 4352 + r * 68 + c], Kn + (size_t)r * 64 + c);
                cpa16(&sV[nb * 4608 + r * 72 + c], Vn + (size_t)r * 64 + c);
            }
            cpa_commit();
            asm volatile("cp.async.wait_group 1;\n");
        } else {
            asm volatile("cp.async.wait_group 0;\n");
        }
        __syncthreads();
        const float* K0 = sK + (kt & 1) * 4352;
        const float* V0 = sV + (kt & 1) * 4608;

        // S = Q @ K^T
        float s[2][8][4];
        #pragma unroll
        for (int mt = 0; mt < 2; mt++)
            #pragma unroll
            for (int nt = 0; nt < 8; nt++)
                #pragma unroll
                for (int e = 0; e < 4; e++) s[mt][nt][e] = 0.f;

        #pragma unroll
        for (int ks = 0; ks < 64; ks += 8) {
            uint32_t a[2][4];
            #pragma unroll
            for (int mt = 0; mt < 2; mt++) {
                int r = m0 + mt * 16;
                a[mt][0] = f2b(sQ[(r + g) * 68 + ks + tg]);
                a[mt][1] = f2b(sQ[(r + g + 8) * 68 + ks + tg]);
                a[mt][2] = f2b(sQ[(r + g) * 68 + ks + tg + 4]);
                a[mt][3] = f2b(sQ[(r + g + 8) * 68 + ks + tg + 4]);
            }
            #pragma unroll
            for (int nt = 0; nt < 8; nt++) {
                uint32_t b0 = f2b(K0[(nt * 8 + g) * 68 + ks + tg]);
                uint32_t b1 = f2b(K0[(nt * 8 + g) * 68 + ks + tg + 4]);
                #pragma unroll
                for (int mt = 0; mt < 2; mt++)
                    mma8(s[mt][nt][0], s[mt][nt][1], s[mt][nt][2], s[mt][nt][3],
                         a[mt][0], a[mt][1], a[mt][2], a[mt][3], b0, b1);
            }
        }

        // causal mask (only tiles that can touch the diagonal)
        if (kt >= 2 * qt) {
            int colbase = kt * 64;
            #pragma unroll
            for (int mt = 0; mt < 2; mt++) {
                int row = qt * 128 + m0 + mt * 16 + g;
                #pragma unroll
                for (int nt = 0; nt < 8; nt++) {
                    int col = colbase + nt * 8 + 2 * tg;
                    if (col > row)         s[mt][nt][0] = -1e30f;
                    if (col + 1 > row)     s[mt][nt][1] = -1e30f;
                    if (col > row + 8)     s[mt][nt][2] = -1e30f;
                    if (col + 1 > row + 8) s[mt][nt][3] = -1e30f;
                }
            }
        }

        // online softmax per 16-row tile (2 row-groups each)
        #pragma unroll
        for (int mt = 0; mt < 2; mt++) {
            float vm0 = -1e30f, vm1 = -1e30f;
            #pragma unroll
            for (int nt = 0; nt < 8; nt++) {
                vm0 = fmaxf(vm0, fmaxf(s[mt][nt][0], s[mt][nt][1]));
                vm1 = fmaxf(vm1, fmaxf(s[mt][nt][2], s[mt][nt][3]));
            }
            vm0 = fmaxf(vm0, __shfl_xor_sync(0xffffffffu, vm0, 1));
            vm0 = fmaxf(vm0, __shfl_xor_sync(0xffffffffu, vm0, 2));
            vm1 = fmaxf(vm1, __shfl_xor_sync(0xffffffffu, vm1, 1));
            vm1 = fmaxf(vm1, __shfl_xor_sync(0xffffffffu, vm1, 2));
            int i0 = mt * 2, i1 = mt * 2 + 1;
            float mn0 = fmaxf(mrow[i0], vm0), mn1 = fmaxf(mrow[i1], vm1);
            float c0 = __expf(mrow[i0] - mn0), c1 = __expf(mrow[i1] - mn1);
            mrow[i0] = mn0; mrow[i1] = mn1;
            float sum0 = 0.f, sum1 = 0.f;
            #pragma unroll
            for (int nt = 0; nt < 8; nt++) {
                s[mt][nt][0] = __expf(s[mt][nt][0] - mn0);
                s[mt][nt][1] = __expf(s[mt][nt][1] - mn0);
                s[mt][nt][2] = __expf(s[mt][nt][2] - mn1);
                s[mt][nt][3] = __expf(s[mt][nt][3] - mn1);
                sum0 += s[mt][nt][0] + s[mt][nt][1];
                sum1 += s[mt][nt][2] + s[mt][nt][3];
            }
            sum0 += __shfl_xor_sync(0xffffffffu, sum0, 1);
            sum0 += __shfl_xor_sync(0xffffffffu, sum0, 2);
            sum1 += __shfl_xor_sync(0xffffffffu, sum1, 1);
            sum1 += __shfl_xor_sync(0xffffffffu, sum1, 2);
            lrow[i0] = lrow[i0] * c0 + sum0;
            lrow[i1] = lrow[i1] * c1 + sum1;
            #pragma unroll
            for (int nt = 0; nt < 8; nt++) {
                o[mt][nt][0] *= c0; o[mt][nt][1] *= c0;
                o[mt][nt][2] *= c1; o[mt][nt][3] *= c1;
            }
        }

        // write P (tf32-rounded)
        #pragma unroll
        for (int mt = 0; mt < 2; mt++) {
            int r = m0 + mt * 16 + g;
            #pragma unroll
            for (int nt = 0; nt < 8; nt++) {
                int c = nt * 8 + 2 * tg;
                *(float2*)&sP[r * 68 + c] =
                    make_float2(to_tf32(s[mt][nt][0]), to_tf32(s[mt][nt][1]));
                *(float2*)&sP[(r + 8) * 68 + c] =
                    make_float2(to_tf32(s[mt][nt][2]), to_tf32(s[mt][nt][3]));
            }
        }
        __syncthreads();

        // O += P @ V
        #pragma unroll
        for (int ks = 0; ks < 64; ks += 8) {
            uint32_t a[2][4];
            #pragma unroll
            for (int mt = 0; mt < 2; mt++) {
                int r = m0 + mt * 16;
                a[mt][0] = f2b(sP[(r + g) * 68 + ks + tg]);
                a[mt][1] = f2b(sP[(r + g + 8) * 68 + ks + tg]);
                a[mt][2] = f2b(sP[(r + g) * 68 + ks + tg + 4]);
                a[mt][3] = f2b(sP[(r + g + 8) * 68 + ks + tg + 4]);
            }
            #pragma unroll
            for (int nt = 0; nt < 8; nt++) {
                uint32_t b0 = f2b(V0[(ks + tg) * 72 + nt * 8 + g]);
                uint32_t b1 = f2b(V0[(ks + tg + 4) * 72 + nt * 8 + g]);
                #pragma unroll
                for (int mt = 0; mt < 2; mt++)
                    mma8(o[mt][nt][0], o[mt][nt][1], o[mt][nt][2], o[mt][nt][3],
                         a[mt][0], a[mt][1], a[mt][2], a[mt][3], b0, b1);
            }
        }
        __syncthreads();   // guard sP rewrite & K/V buffer reuse
    }

    // epilogue: normalize, round, write [bt][h*64+d]
    #pragma unroll
    for (int mt = 0; mt < 2; mt++) {
        int r = m0 + mt * 16 + g;
        int grow = qt * 128 + r;
        float inv0 = 1.f / lrow[mt * 2];
        float inv1 = 1.f / lrow[mt * 2 + 1];
        #pragma unroll
        for (int nt = 0; nt < 8; nt++) {
            int c = h * 64 + nt * 8 + 2 * tg;
            size_t base0 = ((size_t)(b * kT) + grow) * kD + c;
            size_t base1 = ((size_t)(b * kT) + grow + 8) * kD + c;
            *(float2*)&g_att[base0] =
                make_float2(to_tf32(o[mt][nt][0] * inv0), to_tf32(o[mt][nt][1] * inv0));
            *(float2*)&g_att[base1] =
                make_float2(to_tf32(o[mt][nt][2] * inv1), to_tf32(o[mt][nt][3] * inv1));
        }
    }
}

// ---------------------------------------------------------------------------
extern "C" void kernel_launch(void* const* d_in, const int* in_sizes, int n_in,
                              void* d_out, int out_size)
{
    const float* x    = (const float*)d_in[0];
    const float* Wqkv = (const float*)d_in[1];
    const float* Wout = (const float*)d_in[2];
    float* out        = (float*)d_out;

    static bool attr_set = false;
    if (!attr_set) {
        cudaFuncSetAttribute(attn_tf32_kernel,
                             cudaFuncAttributeMaxDynamicSharedMemorySize, ATT_SMEM_BYTES);
        attr_set = true;
    }

    float* d_xr;    cudaGetSymbolAddress((void**)&d_xr, g_xr);
    float* d_wqkvr; cudaGetSymbolAddress((void**)&d_wqkvr, g_wqkvr);
    float* d_woutr; cudaGetSymbolAddress((void**)&d_woutr, g_woutr);
    float* d_qkv;   cudaGetSymbolAddress((void**)&d_qkv, g_qkv);
    float* d_att;   cudaGetSymbolAddress((void**)&d_att, g_att);

    dim3 blk(256);

    // 0) pre-round inputs to tf32 (rna)
    int nx = kBT * kD / 4, nq = kD * kQKVN / 4, nw = kD * kD / 4;
    round_tf32_kernel<<<(nx + 255) / 256, blk>>>(x, d_xr, nx);
    round_tf32_kernel<<<(nq + 255) / 256, blk>>>(Wqkv, d_wqkvr, nq);
    round_tf32_kernel<<<(nw + 255) / 256, blk>>>(Wout, d_woutr, nw);

    // 1) QKV projection
    gemm_tf32_kernel<<<dim3(kQKVN / 128, kBT / 128), blk>>>(d_xr, d_wqkvr, d_qkv,
                                                            kBT, kQKVN, kD);
    // 2) RoPE + head split (rounds q/k/v)
    int rope_threads = kBT * kH * 32;
    rope_kernel<<<(rope_threads + 255) / 256, blk>>>();

    // 3) causal flash attention (tf32 mma)
    attn_tf32_kernel<<<dim3(kT / 128, kB * kH), dim3(128), ATT_SMEM_BYTES>>>();

    // 4) output projection
    gemm_tf32_kernel<<<dim3(kD / 128, kBT / 128), blk>>>(d_att, d_woutr, out,
                                                         kBT, kD, kD);
}

// round 5
// speedup vs baseline: 7.2654x; 1.0269x over previous
#include <cuda_runtime.h>
#include <math.h>
#include <stdint.h>

// Problem dims
constexpr int kB  = 4;
constexpr int kT  = 2048;
constexpr int kD  = 1024;
constexpr int kH  = 16;
constexpr int kDH = 64;
constexpr int kBT = kB * kT;           // 8192
constexpr int kQKVN = 3 * kD;          // 3072

// Scratch
__device__ float g_qkv[(size_t)kBT * kQKVN];     // 96 MB
__device__ float g_q[(size_t)kBT * kD];          // [bh][t][64], tf32-rounded
__device__ float g_k[(size_t)kBT * kD];
__device__ float g_v[(size_t)kBT * kD];
__device__ float g_att[(size_t)kBT * kD];        // [bt][h*64+d], tf32-rounded
__device__ float g_xr[(size_t)kBT * kD];         // tf32-rounded copies
__device__ float g_wqkvr[(size_t)kD * kQKVN];
__device__ float g_woutr[(size_t)kD * kD];

// ---------------------------------------------------------------------------
__device__ __forceinline__ float to_tf32(float x) {
    uint32_t r;
    asm("cvt.rna.tf32.f32 %0, %1;" : "=r"(r) : "f"(x));
    return __uint_as_float(r);
}
__device__ __forceinline__ uint32_t f2b(float x) { return __float_as_uint(x); }

__device__ __forceinline__ void mma8(float& d0, float& d1, float& d2, float& d3,
                                     uint32_t a0, uint32_t a1, uint32_t a2, uint32_t a3,
                                     uint32_t b0, uint32_t b1) {
    asm volatile(
        "mma.sync.aligned.m16n8k8.row.col.f32.tf32.tf32.f32 "
        "{%0,%1,%2,%3}, {%4,%5,%6,%7}, {%8,%9}, {%0,%1,%2,%3};\n"
        : "+f"(d0), "+f"(d1), "+f"(d2), "+f"(d3)
        : "r"(a0), "r"(a1), "r"(a2), "r"(a3), "r"(b0), "r"(b1));
}

__device__ __forceinline__ void cpa16(void* s, const void* g) {
    uint32_t sa = (uint32_t)__cvta_generic_to_shared(s);
    asm volatile("cp.async.cg.shared.global [%0], [%1], 16;\n" :: "r"(sa), "l"(g));
}
__device__ __forceinline__ void cpa_commit() {
    asm volatile("cp.async.commit_group;\n");
}

// ---------------------------------------------------------------------------
__global__ __launch_bounds__(256)
void round_tf32_kernel(const float* __restrict__ in, float* __restrict__ out, int n4)
{
    int i = blockIdx.x * blockDim.x + threadIdx.x;
    if (i >= n4) return;
    float4 v = ((const float4*)in)[i];
    v.x = to_tf32(v.x); v.y = to_tf32(v.y); v.z = to_tf32(v.z); v.w = to_tf32(v.w);
    ((float4*)out)[i] = v;
}

// ---------------------------------------------------------------------------
// tf32 GEMM: C[M,N] = A[M,K] @ B[K,N], row-major, A/B pre-rounded to tf32.
// CTA tile 128x256, BK=16, 256 threads = 8 warps (2x4), warp tile 64x64.
// 3-stage cp.async pipeline, one __syncthreads per k-iter.
// smem is DYNAMIC (81,408 B > 48KB static limit).
// ---------------------------------------------------------------------------
constexpr int GEMM_AS_FLOATS = 3 * 128 * 20;   // 7680
constexpr int GEMM_BS_FLOATS = 3 * 16 * 264;   // 12672
constexpr int GEMM_SMEM_BYTES = (GEMM_AS_FLOATS + GEMM_BS_FLOATS) * 4;  // 81408

__global__ __launch_bounds__(256)
void gemm_tf32_kernel(const float* __restrict__ A, const float* __restrict__ B,
                      float* __restrict__ C, int M, int N, int K)
{
    extern __shared__ float smg[];
    float* As = smg;                    // [3][128][20]
    float* Bs = smg + GEMM_AS_FLOATS;   // [3][16][264]
    auto Asp = [&](int s, int r, int c) -> float& { return As[(s * 128 + r) * 20 + c]; };
    auto Bsp = [&](int s, int r, int c) -> float& { return Bs[(s * 16 + r) * 264 + c]; };

    const int tid  = threadIdx.x;
    const int lane = tid & 31, warp = tid >> 5;
    const int wm = (warp >> 2) * 64, wn = (warp & 3) * 64;
    const int g = lane >> 2, tg = lane & 3;
    const int brow = blockIdx.y * 128, bcol = blockIdx.x * 256;

    float acc[4][8][4];
    #pragma unroll
    for (int a = 0; a < 4; a++)
        #pragma unroll
        for (int b = 0; b < 8; b++)
            #pragma unroll
            for (int c = 0; c < 4; c++) acc[a][b][c] = 0.f;

    const int iters = K >> 4;

    auto load_stage = [&](int s, int k0) {
        #pragma unroll
        for (int u = 0; u < 2; u++) {          // A: 512 float4
            int idx = tid + u * 256;
            int r = idx >> 2, c = (idx & 3) << 2;
            cpa16(&Asp(s, r, c), A + (size_t)(brow + r) * K + k0 + c);
        }
        #pragma unroll
        for (int u = 0; u < 4; u++) {          // B: 1024 float4
            int idx = tid + u * 256;
            int br = idx >> 6, bc = (idx & 63) << 2;
            cpa16(&Bsp(s, br, bc), B + (size_t)(k0 + br) * N + bcol + bc);
        }
    };

    load_stage(0, 0);  cpa_commit();
    load_stage(1, 16); cpa_commit();

    for (int it = 0; it < iters; it++) {
        if (it + 1 < iters) asm volatile("cp.async.wait_group 1;\n");
        else                asm volatile("cp.async.wait_group 0;\n");
        __syncthreads();
        if (it + 2 < iters) {
            load_stage((it + 2) % 3, (it + 2) << 4);
            cpa_commit();
        }
        const int buf = it % 3;

        #pragma unroll
        for (int ks = 0; ks < 16; ks += 8) {
            uint32_t a[4][4];
            #pragma unroll
            for (int mt = 0; mt < 4; mt++) {
                int r = wm + mt * 16;
                a[mt][0] = f2b(Asp(buf, r + g,     ks + tg));
                a[mt][1] = f2b(Asp(buf, r + g + 8, ks + tg));
                a[mt][2] = f2b(Asp(buf, r + g,     ks + tg + 4));
                a[mt][3] = f2b(Asp(buf, r + g + 8, ks + tg + 4));
            }
            #pragma unroll
            for (int nt = 0; nt < 8; nt++) {
                int n0 = wn + nt * 8;
                uint32_t b0 = f2b(Bsp(buf, ks + tg,     n0 + g));
                uint32_t b1 = f2b(Bsp(buf, ks + tg + 4, n0 + g));
                #pragma unroll
                for (int mt = 0; mt < 4; mt++)
                    mma8(acc[mt][nt][0], acc[mt][nt][1], acc[mt][nt][2], acc[mt][nt][3],
                         a[mt][0], a[mt][1], a[mt][2], a[mt][3], b0, b1);
            }
        }
        // no trailing sync: the top-of-next-iter sync (before any cp.async into
        // buf (it+3)%3, which is issued at iter it+1) protects reuse.
    }

    #pragma unroll
    for (int mt = 0; mt < 4; mt++) {
        #pragma unroll
        for (int nt = 0; nt < 8; nt++) {
            int r0 = brow + wm + mt * 16 + g;
            int c0 = bcol + wn + nt * 8 + 2 * tg;
            *(float2*)&C[(size_t)r0 * N + c0]       = make_float2(acc[mt][nt][0], acc[mt][nt][1]);
            *(float2*)&C[(size_t)(r0 + 8) * N + c0] = make_float2(acc[mt][nt][2], acc[mt][nt][3]);
        }
    }
}

// ---------------------------------------------------------------------------
// RoPE + split/transpose + tf32 rounding
// ---------------------------------------------------------------------------
__global__ __launch_bounds__(256)
void rope_kernel()
{
    int idx = blockIdx.x * blockDim.x + threadIdx.x;
    if (idx >= kBT * kH * 32) return;
    int i  = idx & 31;
    int h  = (idx >> 5) & (kH - 1);
    int bt = idx >> 9;
    int t  = bt & (kT - 1);
    int b  = bt >> 11;

    float inv_freq = expf(-((float)(2 * i) / 64.0f) * 9.210340371976184f);
    float ang = (float)t * inv_freq;
    float s, c;
    sincosf(ang, &s, &c);

    size_t src = (size_t)bt * kQKVN + h * kDH + i;
    float q1 = g_qkv[src],        q2 = g_qkv[src + 32];
    float k1 = g_qkv[src + 1024], k2 = g_qkv[src + 1056];
    float v1 = g_qkv[src + 2048], v2 = g_qkv[src + 2080];

    size_t dst = ((size_t)(b * kH + h) * kT + t) * kDH + i;
    g_q[dst]      = to_tf32(q1 * c - q2 * s);
    g_q[dst + 32] = to_tf32(q2 * c + q1 * s);
    g_k[dst]      = to_tf32(k1 * c - k2 * s);
    g_k[dst + 32] = to_tf32(k2 * c + k1 * s);
    g_v[dst]      = to_tf32(v1);
    g_v[dst + 32] = to_tf32(v2);
}

// ---------------------------------------------------------------------------
// Flash attention, tf32 mma. CTA = 128 q rows, 4 warps (32 rows each),
// 64-key tiles, SINGLE-buffered K/V (smem 105.5KB -> 2 CTAs/SM), P via smem.
// smem (floats): sQ[128][68] | sP[128][68] | sK[64][68] | sV[64][72]
// ---------------------------------------------------------------------------
constexpr int ATT_SMEM_FLOATS = 8704 + 8704 + 4352 + 4608;   // 26368
constexpr int ATT_SMEM_BYTES  = ATT_SMEM_FLOATS * 4;         // 105472

__global__ __launch_bounds__(128)
void attn_tf32_kernel()
{
    extern __shared__ float sm[];
    float* sQ = sm;                       // [128][68]
    float* sP = sm + 8704;                // [128][68]
    float* sK = sm + 17408;               // [64][68]
    float* sV = sm + 17408 + 4352;        // [64][72]

    const int qt = blockIdx.x;            // 0..15 (128-row tiles)
    const int bh = blockIdx.y;
    const int b  = bh >> 4, h = bh & 15;
    const int tid = threadIdx.x, lane = tid & 31, warp = tid >> 5;
    const int g = lane >> 2, tg = lane & 3;
    const int m0 = warp * 32;

    const float* Qg = g_q + ((size_t)bh * kT + qt * 128) * kDH;
    const float* Kg = g_k + (size_t)bh * kT * kDH;
    const float* Vg = g_v + (size_t)bh * kT * kDH;

    // Load Q tile (scale by 1/8 — exact power of 2, stays tf32)
    for (int i = tid; i < 2048; i += 128) {
        int r = i >> 4, c = (i & 15) << 2;
        float4 v = *(const float4*)(Qg + r * 64 + c);
        v.x *= 0.125f; v.y *= 0.125f; v.z *= 0.125f; v.w *= 0.125f;
        *(float4*)&sQ[r * 68 + c] = v;
    }

    float o[2][8][4];
    #pragma unroll
    for (int mt = 0; mt < 2; mt++)
        #pragma unroll
        for (int nt = 0; nt < 8; nt++)
            #pragma unroll
            for (int e = 0; e < 4; e++) o[mt][nt][e] = 0.f;
    float mrow[4] = {-1e30f, -1e30f, -1e30f, -1e30f};
    float lrow[4] = {0.f, 0.f, 0.f, 0.f};

    const int nkt = 2 * qt + 2;

    for (int kt = 0; kt < nkt; kt++) {
        __syncthreads();   // prev iter done reading sK/sV/sP (also covers sQ fill)
        const float* Kn = Kg + (size_t)kt * 64 * 64;
        const float* Vn = Vg + (size_t)kt * 64 * 64;
        for (int i = tid; i < 1024; i += 128) {
            int r = i >> 4, c = (i & 15) << 2;
            cpa16(&sK[r * 68 + c], Kn + (size_t)r * 64 + c);
            cpa16(&sV[r * 72 + c], Vn + (size_t)r * 64 + c);
        }
        cpa_commit();
        asm volatile("cp.async.wait_group 0;\n");
        __syncthreads();

        // S = Q @ K^T
        float s[2][8][4];
        #pragma unroll
        for (int mt = 0; mt < 2; mt++)
            #pragma unroll
            for (int nt = 0; nt < 8; nt++)
                #pragma unroll
                for (int e = 0; e < 4; e++) s[mt][nt][e] = 0.f;

        #pragma unroll
        for (int ks = 0; ks < 64; ks += 8) {
            uint32_t a[2][4];
            #pragma unroll
            for (int mt = 0; mt < 2; mt++) {
                int r = m0 + mt * 16;
                a[mt][0] = f2b(sQ[(r + g) * 68 + ks + tg]);
                a[mt][1] = f2b(sQ[(r + g + 8) * 68 + ks + tg]);
                a[mt][2] = f2b(sQ[(r + g) * 68 + ks + tg + 4]);
                a[mt][3] = f2b(sQ[(r + g + 8) * 68 + ks + tg + 4]);
            }
            #pragma unroll
            for (int nt = 0; nt < 8; nt++) {
                uint32_t b0 = f2b(sK[(nt * 8 + g) * 68 + ks + tg]);
                uint32_t b1 = f2b(sK[(nt * 8 + g) * 68 + ks + tg + 4]);
                #pragma unroll
                for (int mt = 0; mt < 2; mt++)
                    mma8(s[mt][nt][0], s[mt][nt][1], s[mt][nt][2], s[mt][nt][3],
                         a[mt][0], a[mt][1], a[mt][2], a[mt][3], b0, b1);
            }
        }

        // causal mask (only tiles that can touch the diagonal)
        if (kt >= 2 * qt) {
            int colbase = kt * 64;
            #pragma unroll
            for (int mt = 0; mt < 2; mt++) {
                int row = qt * 128 + m0 + mt * 16 + g;
                #pragma unroll
                for (int nt = 0; nt < 8; nt++) {
                    int col = colbase + nt * 8 + 2 * tg;
                    if (col > row)         s[mt][nt][0] = -1e30f;
                    if (col + 1 > row)     s[mt][nt][1] = -1e30f;
                    if (col > row + 8)     s[mt][nt][2] = -1e30f;
                    if (col + 1 > row + 8) s[mt][nt][3] = -1e30f;
                }
            }
        }

        // online softmax per 16-row tile (2 row-groups each)
        #pragma unroll
        for (int mt = 0; mt < 2; mt++) {
            float vm0 = -1e30f, vm1 = -1e30f;
            #pragma unroll
            for (int nt = 0; nt < 8; nt++) {
                vm0 = fmaxf(vm0, fmaxf(s[mt][nt][0], s[mt][nt][1]));
                vm1 = fmaxf(vm1, fmaxf(s[mt][nt][2], s[mt][nt][3]));
            }
            vm0 = fmaxf(vm0, __shfl_xor_sync(0xffffffffu, vm0, 1));
            vm0 = fmaxf(vm0, __shfl_xor_sync(0xffffffffu, vm0, 2));
            vm1 = fmaxf(vm1, __shfl_xor_sync(0xffffffffu, vm1, 1));
            vm1 = fmaxf(vm1, __shfl_xor_sync(0xffffffffu, vm1, 2));
            int i0 = mt * 2, i1 = mt * 2 + 1;
            float mn0 = fmaxf(mrow[i0], vm0), mn1 = fmaxf(mrow[i1], vm1);
            float c0 = __expf(mrow[i0] - mn0), c1 = __expf(mrow[i1] - mn1);
            mrow[i0] = mn0; mrow[i1] = mn1;
            float sum0 = 0.f, sum1 = 0.f;
            #pragma unroll
            for (int nt = 0; nt < 8; nt++) {
                s[mt][nt][0] = __expf(s[mt][nt][0] - mn0);
                s[mt][nt][1] = __expf(s[mt][nt][1] - mn0);
                s[mt][nt][2] = __expf(s[mt][nt][2] - mn1);
                s[mt][nt][3] = __expf(s[mt][nt][3] - mn1);
                sum0 += s[mt][nt][0] + s[mt][nt][1];
                sum1 += s[mt][nt][2] + s[mt][nt][3];
            }
            sum0 += __shfl_xor_sync(0xffffffffu, sum0, 1);
            sum0 += __shfl_xor_sync(0xffffffffu, sum0, 2);
            sum1 += __shfl_xor_sync(0xffffffffu, sum1, 1);
            sum1 += __shfl_xor_sync(0xffffffffu, sum1, 2);
            lrow[i0] = lrow[i0] * c0 + sum0;
            lrow[i1] = lrow[i1] * c1 + sum1;
            #pragma unroll
            for (int nt = 0; nt < 8; nt++) {
                o[mt][nt][0] *= c0; o[mt][nt][1] *= c0;
                o[mt][nt][2] *= c1; o[mt][nt][3] *= c1;
            }
        }

        // write P (tf32-rounded)
        #pragma unroll
        for (int mt = 0; mt < 2; mt++) {
            int r = m0 + mt * 16 + g;
            #pragma unroll
            for (int nt = 0; nt < 8; nt++) {
                int c = nt * 8 + 2 * tg;
                *(float2*)&sP[r * 68 + c] =
                    make_float2(to_tf32(s[mt][nt][0]), to_tf32(s[mt][nt][1]));
                *(float2*)&sP[(r + 8) * 68 + c] =
                    make_float2(to_tf32(s[mt][nt][2]), to_tf32(s[mt][nt][3]));
            }
        }
        __syncthreads();

        // O += P @ V
        #pragma unroll
        for (int ks = 0; ks < 64; ks += 8) {
            uint32_t a[2][4];
            #pragma unroll
            for (int mt = 0; mt < 2; mt++) {
                int r = m0 + mt * 16;
                a[mt][0] = f2b(sP[(r + g) * 68 + ks + tg]);
                a[mt][1] = f2b(sP[(r + g + 8) * 68 + ks + tg]);
                a[mt][2] = f2b(sP[(r + g) * 68 + ks + tg + 4]);
                a[mt][3] = f2b(sP[(r + g + 8) * 68 + ks + tg + 4]);
            }
            #pragma unroll
            for (int nt = 0; nt < 8; nt++) {
                uint32_t b0 = f2b(sV[(ks + tg) * 72 + nt * 8 + g]);
                uint32_t b1 = f2b(sV[(ks + tg + 4) * 72 + nt * 8 + g]);
                #pragma unroll
                for (int mt = 0; mt < 2; mt++)
                    mma8(o[mt][nt][0], o[mt][nt][1], o[mt][nt][2], o[mt][nt][3],
                         a[mt][0], a[mt][1], a[mt][2], a[mt][3], b0, b1);
            }
        }
    }

    // epilogue: normalize, round, write [bt][h*64+d]
    #pragma unroll
    for (int mt = 0; mt < 2; mt++) {
        int r = m0 + mt * 16 + g;
        int grow = qt * 128 + r;
        float inv0 = 1.f / lrow[mt * 2];
        float inv1 = 1.f / lrow[mt * 2 + 1];
        #pragma unroll
        for (int nt = 0; nt < 8; nt++) {
            int c = h * 64 + nt * 8 + 2 * tg;
            size_t base0 = ((size_t)(b * kT) + grow) * kD + c;
            size_t base1 = ((size_t)(b * kT) + grow + 8) * kD + c;
            *(float2*)&g_att[base0] =
                make_float2(to_tf32(o[mt][nt][0] * inv0), to_tf32(o[mt][nt][1] * inv0));
            *(float2*)&g_att[base1] =
                make_float2(to_tf32(o[mt][nt][2] * inv1), to_tf32(o[mt][nt][3] * inv1));
        }
    }
}

// ---------------------------------------------------------------------------
extern "C" void kernel_launch(void* const* d_in, const int* in_sizes, int n_in,
                              void* d_out, int out_size)
{
    const float* x    = (const float*)d_in[0];
    const float* Wqkv = (const float*)d_in[1];
    const float* Wout = (const float*)d_in[2];
    float* out        = (float*)d_out;

    static bool attr_set = false;
    if (!attr_set) {
        cudaFuncSetAttribute(attn_tf32_kernel,
                             cudaFuncAttributeMaxDynamicSharedMemorySize, ATT_SMEM_BYTES);
        cudaFuncSetAttribute(gemm_tf32_kernel,
                             cudaFuncAttributeMaxDynamicSharedMemorySize, GEMM_SMEM_BYTES);
        attr_set = true;
    }

    float* d_xr;    cudaGetSymbolAddress((void**)&d_xr, g_xr);
    float* d_wqkvr; cudaGetSymbolAddress((void**)&d_wqkvr, g_wqkvr);
    float* d_woutr; cudaGetSymbolAddress((void**)&d_woutr, g_woutr);
    float* d_qkv;   cudaGetSymbolAddress((void**)&d_qkv, g_qkv);
    float* d_att;   cudaGetSymbolAddress((void**)&d_att, g_att);

    dim3 blk(256);

    // 0) pre-round inputs to tf32 (rna)
    int nx = kBT * kD / 4, nq = kD * kQKVN / 4, nw = kD * kD / 4;
    round_tf32_kernel<<<(nx + 255) / 256, blk>>>(x, d_xr, nx);
    round_tf32_kernel<<<(nq + 255) / 256, blk>>>(Wqkv, d_wqkvr, nq);
    round_tf32_kernel<<<(nw + 255) / 256, blk>>>(Wout, d_woutr, nw);

    // 1) QKV projection: [8192,1024] @ [1024,3072], 128x256 tiles
    gemm_tf32_kernel<<<dim3(kQKVN / 256, kBT / 128), blk, GEMM_SMEM_BYTES>>>(
        d_xr, d_wqkvr, d_qkv, kBT, kQKVN, kD);
    // 2) RoPE + head split (rounds q/k/v)
    int rope_threads = kBT * kH * 32;
    rope_kernel<<<(rope_threads + 255) / 256, blk>>>();

    // 3) causal flash attention (tf32 mma)
    attn_tf32_kernel<<<dim3(kT / 128, kB * kH), dim3(128), ATT_SMEM_BYTES>>>();

    // 4) output projection: [8192,1024] @ [1024,1024]
    gemm_tf32_kernel<<<dim3(kD / 256, kBT / 128), blk, GEMM_SMEM_BYTES>>>(
        d_att, d_woutr, out, kBT, kD, kD);
}

// round 6
// speedup vs baseline: 7.9903x; 1.0998x over previous
#include <cuda_runtime.h>
#include <math.h>
#include <stdint.h>

// Problem dims
constexpr int kB  = 4;
constexpr int kT  = 2048;
constexpr int kD  = 1024;
constexpr int kH  = 16;
constexpr int kDH = 64;
constexpr int kBT = kB * kT;           // 8192
constexpr int kQKVN = 3 * kD;          // 3072

// Scratch
__device__ float g_qkv[(size_t)kBT * kQKVN];     // 96 MB
__device__ float g_q[(size_t)kBT * kD];          // [bh][t][64], tf32-rounded
__device__ float g_k[(size_t)kBT * kD];
__device__ float g_v[(size_t)kBT * kD];
__device__ float g_att[(size_t)kBT * kD];        // [bt][h*64+d], tf32-rounded
__device__ float g_xr[(size_t)kBT * kD];         // tf32-rounded copies
__device__ float g_wqkvr[(size_t)kD * kQKVN];
__device__ float g_woutr[(size_t)kD * kD];

// ---------------------------------------------------------------------------
__device__ __forceinline__ float to_tf32(float x) {
    uint32_t r;
    asm("cvt.rna.tf32.f32 %0, %1;" : "=r"(r) : "f"(x));
    return __uint_as_float(r);
}
__device__ __forceinline__ uint32_t f2b(float x) { return __float_as_uint(x); }

__device__ __forceinline__ void mma8(float& d0, float& d1, float& d2, float& d3,
                                     uint32_t a0, uint32_t a1, uint32_t a2, uint32_t a3,
                                     uint32_t b0, uint32_t b1) {
    asm volatile(
        "mma.sync.aligned.m16n8k8.row.col.f32.tf32.tf32.f32 "
        "{%0,%1,%2,%3}, {%4,%5,%6,%7}, {%8,%9}, {%0,%1,%2,%3};\n"
        : "+f"(d0), "+f"(d1), "+f"(d2), "+f"(d3)
        : "r"(a0), "r"(a1), "r"(a2), "r"(a3), "r"(b0), "r"(b1));
}

__device__ __forceinline__ void cpa16(void* s, const void* g) {
    uint32_t sa = (uint32_t)__cvta_generic_to_shared(s);
    asm volatile("cp.async.cg.shared.global [%0], [%1], 16;\n" :: "r"(sa), "l"(g));
}
__device__ __forceinline__ void cpa_commit() {
    asm volatile("cp.async.commit_group;\n");
}

// ---------------------------------------------------------------------------
__global__ __launch_bounds__(256)
void round_tf32_kernel(const float* __restrict__ in, float* __restrict__ out, int n4)
{
    int i = blockIdx.x * blockDim.x + threadIdx.x;
    if (i >= n4) return;
    float4 v = ((const float4*)in)[i];
    v.x = to_tf32(v.x); v.y = to_tf32(v.y); v.z = to_tf32(v.z); v.w = to_tf32(v.w);
    ((float4*)out)[i] = v;
}

// ---------------------------------------------------------------------------
// tf32 GEMM: C[M,N] = A[M,K] @ B[K,N], row-major, pre-rounded to tf32.
// CTA tile 128x128, BK=32, 256 threads = 8 warps (2x4), warp tile 64x32.
// 3-stage cp.async pipeline (prefetch 64 k ahead), one sync per k-iter.
// regs capped via __launch_bounds__(256, 2) -> 2 CTAs/SM (16 warps).
// smem dynamic: As[3][128][36] + Bs[3][32][136] = 107,520 B.
// ---------------------------------------------------------------------------
constexpr int GEMM_AS_STAGE = 128 * 36;          // 4608 floats
constexpr int GEMM_BS_STAGE = 32 * 136;          // 4352 floats
constexpr int GEMM_AS_FLOATS = 3 * GEMM_AS_STAGE;
constexpr int GEMM_BS_FLOATS = 3 * GEMM_BS_STAGE;
constexpr int GEMM_SMEM_BYTES = (GEMM_AS_FLOATS + GEMM_BS_FLOATS) * 4;  // 107520

__global__ __launch_bounds__(256, 2)
void gemm_tf32_kernel(const float* __restrict__ A, const float* __restrict__ B,
                      float* __restrict__ C, int M, int N, int K)
{
    extern __shared__ float smg[];
    float* As = smg;
    float* Bs = smg + GEMM_AS_FLOATS;
    auto Asp = [&](int s, int r, int c) -> float& { return As[s * GEMM_AS_STAGE + r * 36 + c]; };
    auto Bsp = [&](int s, int r, int c) -> float& { return Bs[s * GEMM_BS_STAGE + r * 136 + c]; };

    const int tid  = threadIdx.x;
    const int lane = tid & 31, warp = tid >> 5;
    const int wm = (warp >> 2) * 64, wn = (warp & 3) * 32;
    const int g = lane >> 2, tg = lane & 3;
    const int brow = blockIdx.y * 128, bcol = blockIdx.x * 128;

    float acc[4][4][4];
    #pragma unroll
    for (int a = 0; a < 4; a++)
        #pragma unroll
        for (int b = 0; b < 4; b++)
            #pragma unroll
            for (int c = 0; c < 4; c++) acc[a][b][c] = 0.f;

    const int iters = K >> 5;   // BK = 32

    auto load_stage = [&](int s, int k0) {
        #pragma unroll
        for (int u = 0; u < 4; u++) {          // A: 128x32 = 1024 float4
            int idx = tid + u * 256;
            int r = idx >> 3, c = (idx & 7) << 2;
            cpa16(&Asp(s, r, c), A + (size_t)(brow + r) * K + k0 + c);
        }
        #pragma unroll
        for (int u = 0; u < 4; u++) {          // B: 32x128 = 1024 float4
            int idx = tid + u * 256;
            int br = idx >> 5, bc = (idx & 31) << 2;
            cpa16(&Bsp(s, br, bc), B + (size_t)(k0 + br) * N + bcol + bc);
        }
    };

    load_stage(0, 0);  cpa_commit();
    load_stage(1, 32); cpa_commit();

    for (int it = 0; it < iters; it++) {
        if (it + 1 < iters) asm volatile("cp.async.wait_group 1;\n");
        else                asm volatile("cp.async.wait_group 0;\n");
        __syncthreads();
        if (it + 2 < iters) {
            load_stage((it + 2) % 3, (it + 2) << 5);
            cpa_commit();
        }
        const int buf = it % 3;

        #pragma unroll
        for (int ks = 0; ks < 32; ks += 8) {
            uint32_t a[4][4];
            #pragma unroll
            for (int mt = 0; mt < 4; mt++) {
                int r = wm + mt * 16;
                a[mt][0] = f2b(Asp(buf, r + g,     ks + tg));
                a[mt][1] = f2b(Asp(buf, r + g + 8, ks + tg));
                a[mt][2] = f2b(Asp(buf, r + g,     ks + tg + 4));
                a[mt][3] = f2b(Asp(buf, r + g + 8, ks + tg + 4));
            }
            #pragma unroll
            for (int nt = 0; nt < 4; nt++) {
                int n0 = wn + nt * 8;
                uint32_t b0 = f2b(Bsp(buf, ks + tg,     n0 + g));
                uint32_t b1 = f2b(Bsp(buf, ks + tg + 4, n0 + g));
                #pragma unroll
                for (int mt = 0; mt < 4; mt++)
                    mma8(acc[mt][nt][0], acc[mt][nt][1], acc[mt][nt][2], acc[mt][nt][3],
                         a[mt][0], a[mt][1], a[mt][2], a[mt][3], b0, b1);
            }
        }
        // no trailing sync: next-iter top sync precedes any overwrite of buf
        // (stage it+3 is only issued at iter it+1, after that sync).
    }

    #pragma unroll
    for (int mt = 0; mt < 4; mt++) {
        #pragma unroll
        for (int nt = 0; nt < 4; nt++) {
            int r0 = brow + wm + mt * 16 + g;
            int c0 = bcol + wn + nt * 8 + 2 * tg;
            *(float2*)&C[(size_t)r0 * N + c0]       = make_float2(acc[mt][nt][0], acc[mt][nt][1]);
            *(float2*)&C[(size_t)(r0 + 8) * N + c0] = make_float2(acc[mt][nt][2], acc[mt][nt][3]);
        }
    }
}

// ---------------------------------------------------------------------------
// RoPE + split/transpose + tf32 rounding
// ---------------------------------------------------------------------------
__global__ __launch_bounds__(256)
void rope_kernel()
{
    int idx = blockIdx.x * blockDim.x + threadIdx.x;
    if (idx >= kBT * kH * 32) return;
    int i  = idx & 31;
    int h  = (idx >> 5) & (kH - 1);
    int bt = idx >> 9;
    int t  = bt & (kT - 1);
    int b  = bt >> 11;

    float inv_freq = expf(-((float)(2 * i) / 64.0f) * 9.210340371976184f);
    float ang = (float)t * inv_freq;
    float s, c;
    sincosf(ang, &s, &c);

    size_t src = (size_t)bt * kQKVN + h * kDH + i;
    float q1 = g_qkv[src],        q2 = g_qkv[src + 32];
    float k1 = g_qkv[src + 1024], k2 = g_qkv[src + 1056];
    float v1 = g_qkv[src + 2048], v2 = g_qkv[src + 2080];

    size_t dst = ((size_t)(b * kH + h) * kT + t) * kDH + i;
    g_q[dst]      = to_tf32(q1 * c - q2 * s);
    g_q[dst + 32] = to_tf32(q2 * c + q1 * s);
    g_k[dst]      = to_tf32(k1 * c - k2 * s);
    g_k[dst + 32] = to_tf32(k2 * c + k1 * s);
    g_v[dst]      = to_tf32(v1);
    g_v[dst + 32] = to_tf32(v2);
}

// ---------------------------------------------------------------------------
// Flash attention, tf32 mma. CTA = 128 q rows, 4 warps (32 rows each),
// 64-key tiles, single-buffered K/V (2 CTAs/SM). Split waits: S=QK^T runs
// while the V tile is still streaming in (separate cp.async groups).
// smem (floats): sQ[128][68] | sP[128][68] | sK[64][68] | sV[64][72]
// ---------------------------------------------------------------------------
constexpr int ATT_SMEM_FLOATS = 8704 + 8704 + 4352 + 4608;   // 26368
constexpr int ATT_SMEM_BYTES  = ATT_SMEM_FLOATS * 4;         // 105472

__global__ __launch_bounds__(128)
void attn_tf32_kernel()
{
    extern __shared__ float sm[];
    float* sQ = sm;                       // [128][68]
    float* sP = sm + 8704;                // [128][68]
    float* sK = sm + 17408;               // [64][68]
    float* sV = sm + 17408 + 4352;        // [64][72]

    const int qt = blockIdx.x;            // 0..15 (128-row tiles)
    const int bh = blockIdx.y;
    const int b  = bh >> 4, h = bh & 15;
    const int tid = threadIdx.x, lane = tid & 31, warp = tid >> 5;
    const int g = lane >> 2, tg = lane & 3;
    const int m0 = warp * 32;

    const float* Qg = g_q + ((size_t)bh * kT + qt * 128) * kDH;
    const float* Kg = g_k + (size_t)bh * kT * kDH;
    const float* Vg = g_v + (size_t)bh * kT * kDH;

    // Load Q tile (scale by 1/8 — exact power of 2, stays tf32)
    for (int i = tid; i < 2048; i += 128) {
        int r = i >> 4, c = (i & 15) << 2;
        float4 v = *(const float4*)(Qg + r * 64 + c);
        v.x *= 0.125f; v.y *= 0.125f; v.z *= 0.125f; v.w *= 0.125f;
        *(float4*)&sQ[r * 68 + c] = v;
    }

    float o[2][8][4];
    #pragma unroll
    for (int mt = 0; mt < 2; mt++)
        #pragma unroll
        for (int nt = 0; nt < 8; nt++)
            #pragma unroll
            for (int e = 0; e < 4; e++) o[mt][nt][e] = 0.f;
    float mrow[4] = {-1e30f, -1e30f, -1e30f, -1e30f};
    float lrow[4] = {0.f, 0.f, 0.f, 0.f};

    const int nkt = 2 * qt + 2;

    for (int kt = 0; kt < nkt; kt++) {
        __syncthreads();   // prev iter done reading sK/sV (also covers sQ fill)
        const float* Kn = Kg + (size_t)kt * 64 * 64;
        const float* Vn = Vg + (size_t)kt * 64 * 64;
        // K group
        for (int i = tid; i < 1024; i += 128) {
            int r = i >> 4, c = (i & 15) << 2;
            cpa16(&sK[r * 68 + c], Kn + (size_t)r * 64 + c);
        }
        cpa_commit();
        // V group (completes later; only needed for PV)
        for (int i = tid; i < 1024; i += 128) {
            int r = i >> 4, c = (i & 15) << 2;
            cpa16(&sV[r * 72 + c], Vn + (size_t)r * 64 + c);
        }
        cpa_commit();
        asm volatile("cp.async.wait_group 1;\n");   // K arrived; V in flight
        __syncthreads();

        // S = Q @ K^T
        float s[2][8][4];
        #pragma unroll
        for (int mt = 0; mt < 2; mt++)
            #pragma unroll
            for (int nt = 0; nt < 8; nt++)
                #pragma unroll
                for (int e = 0; e < 4; e++) s[mt][nt][e] = 0.f;

        #pragma unroll
        for (int ks = 0; ks < 64; ks += 8) {
            uint32_t a[2][4];
            #pragma unroll
            for (int mt = 0; mt < 2; mt++) {
                int r = m0 + mt * 16;
                a[mt][0] = f2b(sQ[(r + g) * 68 + ks + tg]);
                a[mt][1] = f2b(sQ[(r + g + 8) * 68 + ks + tg]);
                a[mt][2] = f2b(sQ[(r + g) * 68 + ks + tg + 4]);
                a[mt][3] = f2b(sQ[(r + g + 8) * 68 + ks + tg + 4]);
            }
            #pragma unroll
            for (int nt = 0; nt < 8; nt++) {
                uint32_t b0 = f2b(sK[(nt * 8 + g) * 68 + ks + tg]);
                uint32_t b1 = f2b(sK[(nt * 8 + g) * 68 + ks + tg + 4]);
                #pragma unroll
                for (int mt = 0; mt < 2; mt++)
                    mma8(s[mt][nt][0], s[mt][nt][1], s[mt][nt][2], s[mt][nt][3],
                         a[mt][0], a[mt][1], a[mt][2], a[mt][3], b0, b1);
            }
        }

        // causal mask (only tiles that can touch the diagonal)
        if (kt >= 2 * qt) {
            int colbase = kt * 64;
            #pragma unroll
            for (int mt = 0; mt < 2; mt++) {
                int row = qt * 128 + m0 + mt * 16 + g;
                #pragma unroll
                for (int nt = 0; nt < 8; nt++) {
                    int col = colbase + nt * 8 + 2 * tg;
                    if (col > row)         s[mt][nt][0] = -1e30f;
                    if (col + 1 > row)     s[mt][nt][1] = -1e30f;
                    if (col > row + 8)     s[mt][nt][2] = -1e30f;
                    if (col + 1 > row + 8) s[mt][nt][3] = -1e30f;
                }
            }
        }

        // online softmax per 16-row tile (2 row-groups each)
        #pragma unroll
        for (int mt = 0; mt < 2; mt++) {
            float vm0 = -1e30f, vm1 = -1e30f;
            #pragma unroll
            for (int nt = 0; nt < 8; nt++) {
                vm0 = fmaxf(vm0, fmaxf(s[mt][nt][0], s[mt][nt][1]));
                vm1 = fmaxf(vm1, fmaxf(s[mt][nt][2], s[mt][nt][3]));
            }
            vm0 = fmaxf(vm0, __shfl_xor_sync(0xffffffffu, vm0, 1));
            vm0 = fmaxf(vm0, __shfl_xor_sync(0xffffffffu, vm0, 2));
            vm1 = fmaxf(vm1, __shfl_xor_sync(0xffffffffu, vm1, 1));
            vm1 = fmaxf(vm1, __shfl_xor_sync(0xffffffffu, vm1, 2));
            int i0 = mt * 2, i1 = mt * 2 + 1;
            float mn0 = fmaxf(mrow[i0], vm0), mn1 = fmaxf(mrow[i1], vm1);
            float c0 = __expf(mrow[i0] - mn0), c1 = __expf(mrow[i1] - mn1);
            mrow[i0] = mn0; mrow[i1] = mn1;
            float sum0 = 0.f, sum1 = 0.f;
            #pragma unroll
            for (int nt = 0; nt < 8; nt++) {
                s[mt][nt][0] = __expf(s[mt][nt][0] - mn0);
                s[mt][nt][1] = __expf(s[mt][nt][1] - mn0);
                s[mt][nt][2] = __expf(s[mt][nt][2] - mn1);
                s[mt][nt][3] = __expf(s[mt][nt][3] - mn1);
                sum0 += s[mt][nt][0] + s[mt][nt][1];
                sum1 += s[mt][nt][2] + s[mt][nt][3];
            }
            sum0 += __shfl_xor_sync(0xffffffffu, sum0, 1);
            sum0 += __shfl_xor_sync(0xffffffffu, sum0, 2);
            sum1 += __shfl_xor_sync(0xffffffffu, sum1, 1);
            sum1 += __shfl_xor_sync(0xffffffffu, sum1, 2);
            lrow[i0] = lrow[i0] * c0 + sum0;
            lrow[i1] = lrow[i1] * c1 + sum1;
            #pragma unroll
            for (int nt = 0; nt < 8; nt++) {
                o[mt][nt][0] *= c0; o[mt][nt][1] *= c0;
                o[mt][nt][2] *= c1; o[mt][nt][3] *= c1;
            }
        }

        // write P (tf32-rounded; own-warp rows only)
        #pragma unroll
        for (int mt = 0; mt < 2; mt++) {
            int r = m0 + mt * 16 + g;
            #pragma unroll
            for (int nt = 0; nt < 8; nt++) {
                int c = nt * 8 + 2 * tg;
                *(float2*)&sP[r * 68 + c] =
                    make_float2(to_tf32(s[mt][nt][0]), to_tf32(s[mt][nt][1]));
                *(float2*)&sP[(r + 8) * 68 + c] =
                    make_float2(to_tf32(s[mt][nt][2]), to_tf32(s[mt][nt][3]));
            }
        }
        asm volatile("cp.async.wait_group 0;\n");   // V arrived
        __syncthreads();                            // V visible to all warps

        // O += P @ V
        #pragma unroll
        for (int ks = 0; ks < 64; ks += 8) {
            uint32_t a[2][4];
            #pragma unroll
            for (int mt = 0; mt < 2; mt++) {
                int r = m0 + mt * 16;
                a[mt][0] = f2b(sP[(r + g) * 68 + ks + tg]);
                a[mt][1] = f2b(sP[(r + g + 8) * 68 + ks + tg]);
                a[mt][2] = f2b(sP[(r + g) * 68 + ks + tg + 4]);
                a[mt][3] = f2b(sP[(r + g + 8) * 68 + ks + tg + 4]);
            }
            #pragma unroll
            for (int nt = 0; nt < 8; nt++) {
                uint32_t b0 = f2b(sV[(ks + tg) * 72 + nt * 8 + g]);
                uint32_t b1 = f2b(sV[(ks + tg + 4) * 72 + nt * 8 + g]);
                #pragma unroll
                for (int mt = 0; mt < 2; mt++)
                    mma8(o[mt][nt][0], o[mt][nt][1], o[mt][nt][2], o[mt][nt][3],
                         a[mt][0], a[mt][1], a[mt][2], a[mt][3], b0, b1);
            }
        }
    }

    // epilogue: normalize, round, write [bt][h*64+d]
    #pragma unroll
    for (int mt = 0; mt < 2; mt++) {
        int r = m0 + mt * 16 + g;
        int grow = qt * 128 + r;
        float inv0 = 1.f / lrow[mt * 2];
        float inv1 = 1.f / lrow[mt * 2 + 1];
        #pragma unroll
        for (int nt = 0; nt < 8; nt++) {
            int c = h * 64 + nt * 8 + 2 * tg;
            size_t base0 = ((size_t)(b * kT) + grow) * kD + c;
            size_t base1 = ((size_t)(b * kT) + grow + 8) * kD + c;
            *(float2*)&g_att[base0] =
                make_float2(to_tf32(o[mt][nt][0] * inv0), to_tf32(o[mt][nt][1] * inv0));
            *(float2*)&g_att[base1] =
                make_float2(to_tf32(o[mt][nt][2] * inv1), to_tf32(o[mt][nt][3] * inv1));
        }
    }
}

// ---------------------------------------------------------------------------
extern "C" void kernel_launch(void* const* d_in, const int* in_sizes, int n_in,
                              void* d_out, int out_size)
{
    const float* x    = (const float*)d_in[0];
    const float* Wqkv = (const float*)d_in[1];
    const float* Wout = (const float*)d_in[2];
    float* out        = (float*)d_out;

    static bool attr_set = false;
    if (!attr_set) {
        cudaFuncSetAttribute(attn_tf32_kernel,
                             cudaFuncAttributeMaxDynamicSharedMemorySize, ATT_SMEM_BYTES);
        cudaFuncSetAttribute(gemm_tf32_kernel,
                             cudaFuncAttributeMaxDynamicSharedMemorySize, GEMM_SMEM_BYTES);
        attr_set = true;
    }

    float* d_xr;    cudaGetSymbolAddress((void**)&d_xr, g_xr);
    float* d_wqkvr; cudaGetSymbolAddress((void**)&d_wqkvr, g_wqkvr);
    float* d_woutr; cudaGetSymbolAddress((void**)&d_woutr, g_woutr);
    float* d_qkv;   cudaGetSymbolAddress((void**)&d_qkv, g_qkv);
    float* d_att;   cudaGetSymbolAddress((void**)&d_att, g_att);

    dim3 blk(256);

    // 0) pre-round inputs to tf32 (rna)
    int nx = kBT * kD / 4, nq = kD * kQKVN / 4, nw = kD * kD / 4;
    round_tf32_kernel<<<(nx + 255) / 256, blk>>>(x, d_xr, nx);
    round_tf32_kernel<<<(nq + 255) / 256, blk>>>(Wqkv, d_wqkvr, nq);
    round_tf32_kernel<<<(nw + 255) / 256, blk>>>(Wout, d_woutr, nw);

    // 1) QKV projection: [8192,1024] @ [1024,3072], 128x128 tiles
    gemm_tf32_kernel<<<dim3(kQKVN / 128, kBT / 128), blk, GEMM_SMEM_BYTES>>>(
        d_xr, d_wqkvr, d_qkv, kBT, kQKVN, kD);
    // 2) RoPE + head split (rounds q/k/v)
    int rope_threads = kBT * kH * 32;
    rope_kernel<<<(rope_threads + 255) / 256, blk>>>();

    // 3) causal flash attention (tf32 mma)
    attn_tf32_kernel<<<dim3(kT / 128, kB * kH), dim3(128), ATT_SMEM_BYTES>>>();

    // 4) output projection: [8192,1024] @ [1024,1024]
    gemm_tf32_kernel<<<dim3(kD / 128, kBT / 128), blk, GEMM_SMEM_BYTES>>>(
        d_att, d_woutr, out, kBT, kD, kD);
}

// round 8
// speedup vs baseline: 13.2191x; 1.6544x over previous
#include <cuda_runtime.h>
#include <cuda_fp16.h>
#include <math.h>
#include <stdint.h>

// Problem dims
constexpr int kB  = 4;
constexpr int kT  = 2048;
constexpr int kD  = 1024;
constexpr int kH  = 16;
constexpr int kDH = 64;
constexpr int kBT = kB * kT;           // 8192
constexpr int kQKVN = 3 * kD;          // 3072

// Scratch
__device__ float  g_qkv[(size_t)kBT * kQKVN];      // 96 MB (gemm1 out, fp32)
__device__ __half g_xh[(size_t)kBT * kD];          // x in fp16
__device__ __half g_wqkvt[(size_t)kQKVN * kD];     // Wqkv^T fp16 [3072][1024]
__device__ __half g_woutt[(size_t)kD * kD];        // Wout^T fp16
__device__ __half g_qh[(size_t)kBT * kD];          // [bh][t][64], scaled 1/8
__device__ __half g_kh[(size_t)kBT * kD];
__device__ __half g_vh[(size_t)kBT * kD];          // [bh][t][64]
__device__ __half g_vt[(size_t)kBT * kD];          // [bh][64][kT] (V transposed)
__device__ __half g_atth[(size_t)kBT * kD];        // [bt][h*64+d]

// ---------------------------------------------------------------------------
__device__ __forceinline__ uint32_t packh2(float a, float b) {
    __half2 h = __floats2half2_rn(a, b);
    return *reinterpret_cast<uint32_t*>(&h);
}

__device__ __forceinline__ void mma16(float& d0, float& d1, float& d2, float& d3,
                                      uint32_t a0, uint32_t a1, uint32_t a2, uint32_t a3,
                                      uint32_t b0, uint32_t b1) {
    asm volatile(
        "mma.sync.aligned.m16n8k16.row.col.f32.f16.f16.f32 "
        "{%0,%1,%2,%3}, {%4,%5,%6,%7}, {%8,%9}, {%0,%1,%2,%3};\n"
        : "+f"(d0), "+f"(d1), "+f"(d2), "+f"(d3)
        : "r"(a0), "r"(a1), "r"(a2), "r"(a3), "r"(b0), "r"(b1));
}

__device__ __forceinline__ void cpa16(void* s, const void* g) {
    uint32_t sa = (uint32_t)__cvta_generic_to_shared(s);
    asm volatile("cp.async.cg.shared.global [%0], [%1], 16;\n" :: "r"(sa), "l"(g));
}
__device__ __forceinline__ void cpa_commit() {
    asm volatile("cp.async.commit_group;\n");
}

// ---------------------------------------------------------------------------
// x (float) -> fp16
__global__ __launch_bounds__(256)
void round_half_kernel(const float* __restrict__ in, __half2* __restrict__ out, int n4)
{
    int i = blockIdx.x * blockDim.x + threadIdx.x;
    if (i >= n4) return;
    float4 v = ((const float4*)in)[i];
    out[2 * i]     = __floats2half2_rn(v.x, v.y);
    out[2 * i + 1] = __floats2half2_rn(v.z, v.w);
}

// W [K][N] float -> W^T [N][K] fp16
__global__ __launch_bounds__(256)
void round_transpose_kernel(const float* __restrict__ in, __half* __restrict__ out,
                            int K, int N)
{
    __shared__ float tile[32][33];
    int k0 = blockIdx.y * 32, n0 = blockIdx.x * 32;
    int tx = threadIdx.x & 31, ty = threadIdx.x >> 5;   // 32 x 8
    #pragma unroll
    for (int r = 0; r < 32; r += 8)
        tile[ty + r][tx] = in[(size_t)(k0 + ty + r) * N + n0 + tx];
    __syncthreads();
    #pragma unroll
    for (int r = 0; r < 32; r += 8)
        out[(size_t)(n0 + ty + r) * K + k0 + tx] = __float2half_rn(tile[tx][ty + r]);
}

// ---------------------------------------------------------------------------
// fp16 GEMM: C[M,N] (fp32) = A[M,K] @ Bt[N,K]^T.  CTA 128x128, BK=32,
// 8 warps (2x4), warp tile 64x32, 3-stage cp.async pipeline.
// smem: As[3][128][40]h + Bs[3][128][40]h = 61,440 B (stride 40h: conflict-free)
// ---------------------------------------------------------------------------
constexpr int GH_TILE_H = 128 * 40;                    // halves per tile
constexpr int GH_STAGE_H = 2 * GH_TILE_H;
constexpr int GH_SMEM_BYTES = 3 * GH_STAGE_H * 2;      // 61440

__global__ __launch_bounds__(256, 2)
void gemm_h_kernel(const __half* __restrict__ A, const __half* __restrict__ Bt,
                   float* __restrict__ C, int M, int N, int K)
{
    extern __shared__ __half smh[];

    const int tid  = threadIdx.x;
    const int lane = tid & 31, warp = tid >> 5;
    const int wm = (warp >> 2) * 64, wn = (warp & 3) * 32;
    const int g = lane >> 2, tg = lane & 3;
    const int brow = blockIdx.y * 128, bcol = blockIdx.x * 128;

    float acc[4][4][4];
    #pragma unroll
    for (int a = 0; a < 4; a++)
        #pragma unroll
        for (int b = 0; b < 4; b++)
            #pragma unroll
            for (int c = 0; c < 4; c++) acc[a][b][c] = 0.f;

    const int iters = K >> 5;   // BK = 32

    auto load_stage = [&](int s, int k0) {
        __half* As = smh + s * GH_STAGE_H;
        __half* Bs = As + GH_TILE_H;
        #pragma unroll
        for (int u = 0; u < 2; u++) {          // A: 128 rows x 4 cp16
            int idx = tid + u * 256;
            int r = idx >> 2, c16 = idx & 3;
            cpa16(As + r * 40 + c16 * 8, A + (size_t)(brow + r) * K + k0 + c16 * 8);
        }
        #pragma unroll
        for (int u = 0; u < 2; u++) {          // B: 128 n-rows x 4 cp16
            int idx = tid + u * 256;
            int r = idx >> 2, c16 = idx & 3;
            cpa16(Bs + r * 40 + c16 * 8, Bt + (size_t)(bcol + r) * K + k0 + c16 * 8);
        }
    };

    load_stage(0, 0);  cpa_commit();
    load_stage(1, 32); cpa_commit();

    for (int it = 0; it < iters; it++) {
        if (it + 1 < iters) asm volatile("cp.async.wait_group 1;\n");
        else                asm volatile("cp.async.wait_group 0;\n");
        __syncthreads();
        if (it + 2 < iters) {
            load_stage((it + 2) % 3, (it + 2) << 5);
            cpa_commit();
        }
        const __half* As = smh + (it % 3) * GH_STAGE_H;
        const __half* Bs = As + GH_TILE_H;

        #pragma unroll
        for (int ks = 0; ks < 32; ks += 16) {
            uint32_t a[4][4];
            #pragma unroll
            for (int mt = 0; mt < 4; mt++) {
                int r = wm + mt * 16;
                a[mt][0] = *(const uint32_t*)(As + (r + g) * 40 + ks + 2 * tg);
                a[mt][1] = *(const uint32_t*)(As + (r + g + 8) * 40 + ks + 2 * tg);
                a[mt][2] = *(const uint32_t*)(As + (r + g) * 40 + ks + 2 * tg + 8);
                a[mt][3] = *(const uint32_t*)(As + (r + g + 8) * 40 + ks + 2 * tg + 8);
            }
            #pragma unroll
            for (int nt = 0; nt < 4; nt++) {
                int n0 = wn + nt * 8;
                uint32_t b0 = *(const uint32_t*)(Bs + (n0 + g) * 40 + ks + 2 * tg);
                uint32_t b1 = *(const uint32_t*)(Bs + (n0 + g) * 40 + ks + 2 * tg + 8);
                #pragma unroll
                for (int mt = 0; mt < 4; mt++)
                    mma16(acc[mt][nt][0], acc[mt][nt][1], acc[mt][nt][2], acc[mt][nt][3],
                          a[mt][0], a[mt][1], a[mt][2], a[mt][3], b0, b1);
            }
        }
    }

    #pragma unroll
    for (int mt = 0; mt < 4; mt++) {
        #pragma unroll
        for (int nt = 0; nt < 4; nt++) {
            int r0 = brow + wm + mt * 16 + g;
            int c0 = bcol + wn + nt * 8 + 2 * tg;
            *(float2*)&C[(size_t)r0 * N + c0]       = make_float2(acc[mt][nt][0], acc[mt][nt][1]);
            *(float2*)&C[(size_t)(r0 + 8) * N + c0] = make_float2(acc[mt][nt][2], acc[mt][nt][3]);
        }
    }
}

// ---------------------------------------------------------------------------
// RoPE + split/transpose; outputs fp16; folds 1/8 softmax scale into Q.
// ---------------------------------------------------------------------------
__global__ __launch_bounds__(256)
void rope_kernel()
{
    int idx = blockIdx.x * blockDim.x + threadIdx.x;
    if (idx >= kBT * kH * 32) return;
    int i  = idx & 31;
    int h  = (idx >> 5) & (kH - 1);
    int bt = idx >> 9;
    int t  = bt & (kT - 1);
    int b  = bt >> 11;

    float inv_freq = expf(-((float)(2 * i) / 64.0f) * 9.210340371976184f);
    float ang = (float)t * inv_freq;
    float s, c;
    sincosf(ang, &s, &c);

    size_t src = (size_t)bt * kQKVN + h * kDH + i;
    float q1 = g_qkv[src],        q2 = g_qkv[src + 32];
    float k1 = g_qkv[src + 1024], k2 = g_qkv[src + 1056];
    float v1 = g_qkv[src + 2048], v2 = g_qkv[src + 2080];

    size_t dst = ((size_t)(b * kH + h) * kT + t) * kDH + i;
    g_qh[dst]      = __float2half_rn(0.125f * (q1 * c - q2 * s));
    g_qh[dst + 32] = __float2half_rn(0.125f * (q2 * c + q1 * s));
    g_kh[dst]      = __float2half_rn(k1 * c - k2 * s);
    g_kh[dst + 32] = __float2half_rn(k2 * c + k1 * s);
    g_vh[dst]      = __float2half_rn(v1);
    g_vh[dst + 32] = __float2half_rn(v2);
}

// V [bh][t][64] -> Vt [bh][64][kT]
__global__ __launch_bounds__(256)
void vtrans_kernel()
{
    __shared__ uint16_t tl[64][66];
    int t0 = blockIdx.x * 64;
    int bh = blockIdx.y;
    const uint32_t* src = (const uint32_t*)(g_vh + ((size_t)bh * kT + t0) * 64);
    #pragma unroll
    for (int it = 0; it < 8; it++) {
        int idx = threadIdx.x + it * 256;
        int r = idx >> 5, c2 = idx & 31;
        uint32_t v = src[r * 32 + c2];
        tl[r][2 * c2]     = (uint16_t)(v & 0xFFFF);
        tl[r][2 * c2 + 1] = (uint16_t)(v >> 16);
    }
    __syncthreads();
    #pragma unroll
    for (int it = 0; it < 8; it++) {
        int idx = threadIdx.x + it * 256;
        int d = idx >> 5, c2 = idx & 31;
        int t = 2 * c2;
        uint32_t v = (uint32_t)tl[t][d] | ((uint32_t)tl[t + 1][d] << 16);
        *(uint32_t*)(g_vt + ((size_t)(bh * 64 + d)) * kT + t0 + t) = v;
    }
}

// ---------------------------------------------------------------------------
// Flash attention, fp16 mma. CTA = 128 q rows, 4 warps. Q and P live in
// registers (m16n8k16 A-frag == concat of two m16n8 D-frags). smem holds only
// K and V^T tiles, double-buffered (2-stage cp.async pipeline). 36,864 B.
// ---------------------------------------------------------------------------
constexpr int ATT_TILE_H = 64 * 72;                    // halves per tile
constexpr int ATT_STAGE_H = 2 * ATT_TILE_H;            // K + Vt
constexpr int ATT_SMEM_BYTES = 2 * ATT_STAGE_H * 2;    // 36864

__global__ __launch_bounds__(128)
void attn_h_kernel()
{
    extern __shared__ __half smh[];

    const int qt = blockIdx.x;
    const int bh = blockIdx.y;
    const int b  = bh >> 4, h = bh & 15;
    const int tid = threadIdx.x, lane = tid & 31, warp = tid >> 5;
    const int g = lane >> 2, tg = lane & 3;
    const int m0 = warp * 32;

    const __half* Qg = g_qh + ((size_t)bh * kT + qt * 128) * kDH;
    const __half* Kg = g_kh + (size_t)bh * kT * kDH;
    const __half* Vt = g_vt + (size_t)bh * 64 * kT;

    // Q fragments in registers: [kk][mt][4]
    uint32_t qf[4][2][4];
    #pragma unroll
    for (int kk = 0; kk < 4; kk++)
        #pragma unroll
        for (int mt = 0; mt < 2; mt++) {
            int r0 = m0 + mt * 16 + g;
            int k = kk * 16 + 2 * tg;
            qf[kk][mt][0] = *(const uint32_t*)(Qg + (size_t)r0 * 64 + k);
            qf[kk][mt][1] = *(const uint32_t*)(Qg + (size_t)(r0 + 8) * 64 + k);
            qf[kk][mt][2] = *(const uint32_t*)(Qg + (size_t)r0 * 64 + k + 8);
            qf[kk][mt][3] = *(const uint32_t*)(Qg + (size_t)(r0 + 8) * 64 + k + 8);
        }

    float o[2][8][4];
    #pragma unroll
    for (int mt = 0; mt < 2; mt++)
        #pragma unroll
        for (int nt = 0; nt < 8; nt++)
            #pragma unroll
            for (int e = 0; e < 4; e++) o[mt][nt][e] = 0.f;
    float mrow[4] = {-1e30f, -1e30f, -1e30f, -1e30f};
    float lrow[4] = {0.f, 0.f, 0.f, 0.f};

    const int nkt = 2 * qt + 2;

    auto load_stage = [&](int s, int kt) {
        __half* sK = smh + s * ATT_STAGE_H;
        __half* sV = sK + ATT_TILE_H;
        int bt0 = kt * 64;
        #pragma unroll
        for (int u = 0; u < 4; u++) {
            int idx = tid + u * 128;
            int r = idx >> 3, c16 = idx & 7;
            cpa16(sK + r * 72 + c16 * 8,
                  Kg + ((size_t)(bt0 + r)) * 64 + c16 * 8);
        }
        #pragma unroll
        for (int u = 0; u < 4; u++) {
            int idx = tid + u * 128;
            int r = idx >> 3, c16 = idx & 7;
            cpa16(sV + r * 72 + c16 * 8,
                  Vt + (size_t)r * kT + bt0 + c16 * 8);
        }
    };

    load_stage(0, 0);
    cpa_commit();

    for (int kt = 0; kt < nkt; kt++) {
        __syncthreads();   // everyone done reading buffer (kt+1)&1 (iter kt-1)
        if (kt + 1 < nkt) {
            load_stage((kt + 1) & 1, kt + 1);
            cpa_commit();
            asm volatile("cp.async.wait_group 1;\n");
        } else {
            asm volatile("cp.async.wait_group 0;\n");
        }
        __syncthreads();
        const __half* sK = smh + (kt & 1) * ATT_STAGE_H;
        const __half* sV = sK + ATT_TILE_H;

        // S = Q @ K^T
        float s[2][8][4];
        #pragma unroll
        for (int mt = 0; mt < 2; mt++)
            #pragma unroll
            for (int nt = 0; nt < 8; nt++)
                #pragma unroll
                for (int e = 0; e < 4; e++) s[mt][nt][e] = 0.f;

        #pragma unroll
        for (int kk = 0; kk < 4; kk++) {
            #pragma unroll
            for (int nt = 0; nt < 8; nt++) {
                uint32_t b0 = *(const uint32_t*)(sK + (nt * 8 + g) * 72 + kk * 16 + 2 * tg);
                uint32_t b1 = *(const uint32_t*)(sK + (nt * 8 + g) * 72 + kk * 16 + 2 * tg + 8);
                #pragma unroll
                for (int mt = 0; mt < 2; mt++)
                    mma16(s[mt][nt][0], s[mt][nt][1], s[mt][nt][2], s[mt][nt][3],
                          qf[kk][mt][0], qf[kk][mt][1], qf[kk][mt][2], qf[kk][mt][3],
                          b0, b1);
            }
        }

        // causal mask
        if (kt >= 2 * qt) {
            int colbase = kt * 64;
            #pragma unroll
            for (int mt = 0; mt < 2; mt++) {
                int row = qt * 128 + m0 + mt * 16 + g;
                #pragma unroll
                for (int nt = 0; nt < 8; nt++) {
                    int col = colbase + nt * 8 + 2 * tg;
                    if (col > row)         s[mt][nt][0] = -1e30f;
                    if (col + 1 > row)     s[mt][nt][1] = -1e30f;
                    if (col > row + 8)     s[mt][nt][2] = -1e30f;
                    if (col + 1 > row + 8) s[mt][nt][3] = -1e30f;
                }
            }
        }

        // online softmax
        uint32_t p2[2][8][2];
        #pragma unroll
        for (int mt = 0; mt < 2; mt++) {
            float vm0 = -1e30f, vm1 = -1e30f;
            #pragma unroll
            for (int nt = 0; nt < 8; nt++) {
                vm0 = fmaxf(vm0, fmaxf(s[mt][nt][0], s[mt][nt][1]));
                vm1 = fmaxf(vm1, fmaxf(s[mt][nt][2], s[mt][nt][3]));
            }
            vm0 = fmaxf(vm0, __shfl_xor_sync(0xffffffffu, vm0, 1));
            vm0 = fmaxf(vm0, __shfl_xor_sync(0xffffffffu, vm0, 2));
            vm1 = fmaxf(vm1, __shfl_xor_sync(0xffffffffu, vm1, 1));
            vm1 = fmaxf(vm1, __shfl_xor_sync(0xffffffffu, vm1, 2));
            int i0 = mt * 2, i1 = mt * 2 + 1;
            float mn0 = fmaxf(mrow[i0], vm0), mn1 = fmaxf(mrow[i1], vm1);
            float c0 = __expf(mrow[i0] - mn0), c1 = __expf(mrow[i1] - mn1);
            mrow[i0] = mn0; mrow[i1] = mn1;
            float sum0 = 0.f, sum1 = 0.f;
            #pragma unroll
            for (int nt = 0; nt < 8; nt++) {
                float e0 = __expf(s[mt][nt][0] - mn0);
                float e1 = __expf(s[mt][nt][1] - mn0);
                float e2 = __expf(s[mt][nt][2] - mn1);
                float e3 = __expf(s[mt][nt][3] - mn1);
                sum0 += e0 + e1; sum1 += e2 + e3;
                p2[mt][nt][0] = packh2(e0, e1);
                p2[mt][nt][1] = packh2(e2, e3);
            }
            sum0 += __shfl_xor_sync(0xffffffffu, sum0, 1);
            sum0 += __shfl_xor_sync(0xffffffffu, sum0, 2);
            sum1 += __shfl_xor_sync(0xffffffffu, sum1, 1);
            sum1 += __shfl_xor_sync(0xffffffffu, sum1, 2);
            lrow[i0] = lrow[i0] * c0 + sum0;
            lrow[i1] = lrow[i1] * c1 + sum1;
            #pragma unroll
            for (int nt = 0; nt < 8; nt++) {
                o[mt][nt][0] *= c0; o[mt][nt][1] *= c0;
                o[mt][nt][2] *= c1; o[mt][nt][3] *= c1;
            }
        }

        // O += P @ V   (P A-frags straight from the score D-frags)
        #pragma unroll
        for (int kk = 0; kk < 4; kk++) {
            int nt0 = kk * 2;
            #pragma unroll
            for (int nt = 0; nt < 8; nt++) {
                uint32_t b0 = *(const uint32_t*)(sV + (nt * 8 + g) * 72 + kk * 16 + 2 * tg);
                uint32_t b1 = *(const uint32_t*)(sV + (nt * 8 + g) * 72 + kk * 16 + 2 * tg + 8);
                #pragma unroll
                for (int mt = 0; mt < 2; mt++)
                    mma16(o[mt][nt][0], o[mt][nt][1], o[mt][nt][2], o[mt][nt][3],
                          p2[mt][nt0][0], p2[mt][nt0][1],
                          p2[mt][nt0 + 1][0], p2[mt][nt0 + 1][1],
                          b0, b1);
            }
        }
    }

    // epilogue: normalize, write fp16 [bt][h*64+d]
    #pragma unroll
    for (int mt = 0; mt < 2; mt++) {
        int r = m0 + mt * 16 + g;
        int grow = qt * 128 + r;
        float inv0 = 1.f / lrow[mt * 2];
        float inv1 = 1.f / lrow[mt * 2 + 1];
        #pragma unroll
        for (int nt = 0; nt < 8; nt++) {
            int c = h * 64 + nt * 8 + 2 * tg;
            size_t base0 = ((size_t)(b * kT) + grow) * kD + c;
            size_t base1 = ((size_t)(b * kT) + grow + 8) * kD + c;
            *(uint32_t*)&g_atth[base0] = packh2(o[mt][nt][0] * inv0, o[mt][nt][1] * inv0);
            *(uint32_t*)&g_atth[base1] = packh2(o[mt][nt][2] * inv1, o[mt][nt][3] * inv1);
        }
    }
}

// ---------------------------------------------------------------------------
extern "C" void kernel_launch(void* const* d_in, const int* in_sizes, int n_in,
                              void* d_out, int out_size)
{
    const float* x    = (const float*)d_in[0];
    const float* Wqkv = (const float*)d_in[1];
    const float* Wout = (const float*)d_in[2];
    float* out        = (float*)d_out;

    static bool attr_set = false;
    if (!attr_set) {
        cudaFuncSetAttribute(gemm_h_kernel,
                             cudaFuncAttributeMaxDynamicSharedMemorySize, GH_SMEM_BYTES);
        cudaFuncSetAttribute(attn_h_kernel,
                             cudaFuncAttributeMaxDynamicSharedMemorySize, ATT_SMEM_BYTES);
        attr_set = true;
    }

    __half* d_xh;    cudaGetSymbolAddress((void**)&d_xh, g_xh);
    __half* d_wqkvt; cudaGetSymbolAddress((void**)&d_wqkvt, g_wqkvt);
    __half* d_woutt; cudaGetSymbolAddress((void**)&d_woutt, g_woutt);
    __half* d_atth;  cudaGetSymbolAddress((void**)&d_atth, g_atth);
    float*  d_qkv;   cudaGetSymbolAddress((void**)&d_qkv, g_qkv);

    dim3 blk(256);

    // 0) convert inputs
    int nx = kBT * kD / 4;
    round_half_kernel<<<(nx + 255) / 256, blk>>>(x, (__half2*)d_xh, nx);
    round_transpose_kernel<<<dim3(kQKVN / 32, kD / 32), blk>>>(Wqkv, d_wqkvt, kD, kQKVN);
    round_transpose_kernel<<<dim3(kD / 32, kD / 32), blk>>>(Wout, d_woutt, kD, kD);

    // 1) QKV projection (fp16 mma)
    gemm_h_kernel<<<dim3(kQKVN / 128, kBT / 128), blk, GH_SMEM_BYTES>>>(
        d_xh, d_wqkvt, d_qkv, kBT, kQKVN, kD);

    // 2) RoPE + head split (fp16 out, Q pre-scaled)
    int rope_threads = kBT * kH * 32;
    rope_kernel<<<(rope_threads + 255) / 256, blk>>>();

    // 2b) V transpose
    vtrans_kernel<<<dim3(kT / 64, kB * kH), blk>>>();

    // 3) causal flash attention (fp16 mma, register Q/P)
    attn_h_kernel<<<dim3(kT / 128, kB * kH), dim3(128), ATT_SMEM_BYTES>>>();

    // 4) output projection (fp16 mma)
    gemm_h_kernel<<<dim3(kD / 128, kBT / 128), blk, GH_SMEM_BYTES>>>(
        d_atth, d_woutt, out, kBT, kD, kD);
}

// round 9
// speedup vs baseline: 14.4116x; 1.0902x over previous
#include <cuda_runtime.h>
#include <cuda_fp16.h>
#include <math.h>
#include <stdint.h>

// Problem dims
constexpr int kB  = 4;
constexpr int kT  = 2048;
constexpr int kD  = 1024;
constexpr int kH  = 16;
constexpr int kDH = 64;
constexpr int kBT = kB * kT;           // 8192
constexpr int kQKVN = 3 * kD;          // 3072

// Scratch
__device__ float  g_qkv[(size_t)kBT * kQKVN];      // 96 MB (gemm1 out, fp32)
__device__ __half g_xh[(size_t)kBT * kD];          // x in fp16
__device__ __half g_wqkvt[(size_t)kQKVN * kD];     // Wqkv^T fp16 [3072][1024]
__device__ __half g_woutt[(size_t)kD * kD];        // Wout^T fp16
__device__ __half g_qh[(size_t)kBT * kD];          // [bh][t][64], scaled 1/8
__device__ __half g_kh[(size_t)kBT * kD];
__device__ __half g_vh[(size_t)kBT * kD];          // [bh][t][64]
__device__ __half g_vt[(size_t)kBT * kD];          // [bh][64][kT] (V transposed)
__device__ __half g_atth[(size_t)kBT * kD];        // [bt][h*64+d]

// ---------------------------------------------------------------------------
__device__ __forceinline__ uint32_t packh2(float a, float b) {
    __half2 h = __floats2half2_rn(a, b);
    return *reinterpret_cast<uint32_t*>(&h);
}
__device__ __forceinline__ uint32_t smem_u32(const void* p) {
    return (uint32_t)__cvta_generic_to_shared(p);
}

__device__ __forceinline__ void mma16(float& d0, float& d1, float& d2, float& d3,
                                      uint32_t a0, uint32_t a1, uint32_t a2, uint32_t a3,
                                      uint32_t b0, uint32_t b1) {
    asm volatile(
        "mma.sync.aligned.m16n8k16.row.col.f32.f16.f16.f32 "
        "{%0,%1,%2,%3}, {%4,%5,%6,%7}, {%8,%9}, {%0,%1,%2,%3};\n"
        : "+f"(d0), "+f"(d1), "+f"(d2), "+f"(d3)
        : "r"(a0), "r"(a1), "r"(a2), "r"(a3), "r"(b0), "r"(b1));
}

// 4-tile ldmatrix: tiles 0..3 from lanes 0-7 / 8-15 / 16-23 / 24-31 addresses.
__device__ __forceinline__ void ldsm4(uint32_t& r0, uint32_t& r1, uint32_t& r2,
                                      uint32_t& r3, uint32_t a) {
    asm volatile("ldmatrix.sync.aligned.m8n8.x4.shared.b16 {%0,%1,%2,%3}, [%4];"
        : "=r"(r0), "=r"(r1), "=r"(r2), "=r"(r3) : "r"(a));
}

__device__ __forceinline__ void cpa16(void* s, const void* g) {
    uint32_t sa = (uint32_t)__cvta_generic_to_shared(s);
    asm volatile("cp.async.cg.shared.global [%0], [%1], 16;\n" :: "r"(sa), "l"(g));
}
__device__ __forceinline__ void cpa_commit() {
    asm volatile("cp.async.commit_group;\n");
}

// ---------------------------------------------------------------------------
__global__ __launch_bounds__(256)
void round_half_kernel(const float* __restrict__ in, __half2* __restrict__ out, int n4)
{
    int i = blockIdx.x * blockDim.x + threadIdx.x;
    if (i >= n4) return;
    float4 v = ((const float4*)in)[i];
    out[2 * i]     = __floats2half2_rn(v.x, v.y);
    out[2 * i + 1] = __floats2half2_rn(v.z, v.w);
}

// W [K][N] float -> W^T [N][K] fp16
__global__ __launch_bounds__(256)
void round_transpose_kernel(const float* __restrict__ in, __half* __restrict__ out,
                            int K, int N)
{
    __shared__ float tile[32][33];
    int k0 = blockIdx.y * 32, n0 = blockIdx.x * 32;
    int tx = threadIdx.x & 31, ty = threadIdx.x >> 5;   // 32 x 8
    #pragma unroll
    for (int r = 0; r < 32; r += 8)
        tile[ty + r][tx] = in[(size_t)(k0 + ty + r) * N + n0 + tx];
    __syncthreads();
    #pragma unroll
    for (int r = 0; r < 32; r += 8)
        out[(size_t)(n0 + ty + r) * K + k0 + tx] = __float2half_rn(tile[tx][ty + r]);
}

// ---------------------------------------------------------------------------
// fp16 GEMM with ldmatrix fragment loads. CTA 128x128, BK=32, 8 warps (2x4),
// warp tile 64x32, 3-stage cp.async pipeline.
// smem: As[3][128][40]h + Bs[3][128][40]h = 61,440 B
// ---------------------------------------------------------------------------
constexpr int GH_TILE_H = 128 * 40;
constexpr int GH_STAGE_H = 2 * GH_TILE_H;
constexpr int GH_SMEM_BYTES = 3 * GH_STAGE_H * 2;      // 61440

__global__ __launch_bounds__(256, 2)
void gemm_h_kernel(const __half* __restrict__ A, const __half* __restrict__ Bt,
                   float* __restrict__ C, int M, int N, int K)
{
    extern __shared__ __half smh[];

    const int tid  = threadIdx.x;
    const int lane = tid & 31, warp = tid >> 5;
    const int wm = (warp >> 2) * 64, wn = (warp & 3) * 32;
    const int g = lane >> 2, tg = lane & 3;
    const int brow = blockIdx.y * 128, bcol = blockIdx.x * 128;

    // ldmatrix per-lane row/k offsets
    const int rowA = wm + (lane & 15);
    const int kA   = (lane >> 4) << 3;                       // 0 or 8
    const int rowB = wn + (lane & 7) + ((lane >> 4) << 3);   // +8 rows for lanes>=16
    const int kBo  = ((lane >> 3) & 1) << 3;                 // +8 k for lanes 8-15/24-31

    const uint32_t smbase = smem_u32(smh);
    const uint32_t aOff = (uint32_t)(rowA * 40 + kA) * 2;
    const uint32_t bOff = (uint32_t)GH_TILE_H * 2 + (uint32_t)(rowB * 40 + kBo) * 2;

    float acc[4][4][4];
    #pragma unroll
    for (int a = 0; a < 4; a++)
        #pragma unroll
        for (int b = 0; b < 4; b++)
            #pragma unroll
            for (int c = 0; c < 4; c++) acc[a][b][c] = 0.f;

    const int iters = K >> 5;   // BK = 32

    auto load_stage = [&](int s, int k0) {
        __half* As = smh + s * GH_STAGE_H;
        __half* Bs = As + GH_TILE_H;
        #pragma unroll
        for (int u = 0; u < 2; u++) {
            int idx = tid + u * 256;
            int r = idx >> 2, c16 = idx & 3;
            cpa16(As + r * 40 + c16 * 8, A + (size_t)(brow + r) * K + k0 + c16 * 8);
        }
        #pragma unroll
        for (int u = 0; u < 2; u++) {
            int idx = tid + u * 256;
            int r = idx >> 2, c16 = idx & 3;
            cpa16(Bs + r * 40 + c16 * 8, Bt + (size_t)(bcol + r) * K + k0 + c16 * 8);
        }
    };

    load_stage(0, 0);  cpa_commit();
    load_stage(1, 32); cpa_commit();

    for (int it = 0; it < iters; it++) {
        if (it + 1 < iters) asm volatile("cp.async.wait_group 1;\n");
        else                asm volatile("cp.async.wait_group 0;\n");
        __syncthreads();
        if (it + 2 < iters) {
            load_stage((it + 2) % 3, (it + 2) << 5);
            cpa_commit();
        }
        const uint32_t stg = smbase + (uint32_t)((it % 3) * GH_STAGE_H) * 2;
        const uint32_t aAddr = stg + aOff;
        const uint32_t bAddr = stg + bOff;

        #pragma unroll
        for (int ks = 0; ks < 32; ks += 16) {
            uint32_t a[4][4], bq[2][4];
            #pragma unroll
            for (int mt = 0; mt < 4; mt++)
                ldsm4(a[mt][0], a[mt][1], a[mt][2], a[mt][3],
                      aAddr + (uint32_t)(mt * 16 * 40 + ks) * 2);
            #pragma unroll
            for (int np = 0; np < 2; np++)
                ldsm4(bq[np][0], bq[np][1], bq[np][2], bq[np][3],
                      bAddr + (uint32_t)(np * 16 * 40 + ks) * 2);
            #pragma unroll
            for (int nt = 0; nt < 4; nt++) {
                uint32_t b0 = bq[nt >> 1][(nt & 1) * 2];
                uint32_t b1 = bq[nt >> 1][(nt & 1) * 2 + 1];
                #pragma unroll
                for (int mt = 0; mt < 4; mt++)
                    mma16(acc[mt][nt][0], acc[mt][nt][1], acc[mt][nt][2], acc[mt][nt][3],
                          a[mt][0], a[mt][1], a[mt][2], a[mt][3], b0, b1);
            }
        }
    }

    #pragma unroll
    for (int mt = 0; mt < 4; mt++) {
        #pragma unroll
        for (int nt = 0; nt < 4; nt++) {
            int r0 = brow + wm + mt * 16 + g;
            int c0 = bcol + wn + nt * 8 + 2 * tg;
            *(float2*)&C[(size_t)r0 * N + c0]       = make_float2(acc[mt][nt][0], acc[mt][nt][1]);
            *(float2*)&C[(size_t)(r0 + 8) * N + c0] = make_float2(acc[mt][nt][2], acc[mt][nt][3]);
        }
    }
}

// ---------------------------------------------------------------------------
// RoPE + split/transpose; outputs fp16; folds 1/8 softmax scale into Q.
// ---------------------------------------------------------------------------
__global__ __launch_bounds__(256)
void rope_kernel()
{
    int idx = blockIdx.x * blockDim.x + threadIdx.x;
    if (idx >= kBT * kH * 32) return;
    int i  = idx & 31;
    int h  = (idx >> 5) & (kH - 1);
    int bt = idx >> 9;
    int t  = bt & (kT - 1);
    int b  = bt >> 11;

    float inv_freq = expf(-((float)(2 * i) / 64.0f) * 9.210340371976184f);
    float ang = (float)t * inv_freq;
    float s, c;
    sincosf(ang, &s, &c);

    size_t src = (size_t)bt * kQKVN + h * kDH + i;
    float q1 = g_qkv[src],        q2 = g_qkv[src + 32];
    float k1 = g_qkv[src + 1024], k2 = g_qkv[src + 1056];
    float v1 = g_qkv[src + 2048], v2 = g_qkv[src + 2080];

    size_t dst = ((size_t)(b * kH + h) * kT + t) * kDH + i;
    g_qh[dst]      = __float2half_rn(0.125f * (q1 * c - q2 * s));
    g_qh[dst + 32] = __float2half_rn(0.125f * (q2 * c + q1 * s));
    g_kh[dst]      = __float2half_rn(k1 * c - k2 * s);
    g_kh[dst + 32] = __float2half_rn(k2 * c + k1 * s);
    g_vh[dst]      = __float2half_rn(v1);
    g_vh[dst + 32] = __float2half_rn(v2);
}

// V [bh][t][64] -> Vt [bh][64][kT]
__global__ __launch_bounds__(256)
void vtrans_kernel()
{
    __shared__ uint16_t tl[64][66];
    int t0 = blockIdx.x * 64;
    int bh = blockIdx.y;
    const uint32_t* src = (const uint32_t*)(g_vh + ((size_t)bh * kT + t0) * 64);
    #pragma unroll
    for (int it = 0; it < 8; it++) {
        int idx = threadIdx.x + it * 256;
        int r = idx >> 5, c2 = idx & 31;
        uint32_t v = src[r * 32 + c2];
        tl[r][2 * c2]     = (uint16_t)(v & 0xFFFF);
        tl[r][2 * c2 + 1] = (uint16_t)(v >> 16);
    }
    __syncthreads();
    #pragma unroll
    for (int it = 0; it < 8; it++) {
        int idx = threadIdx.x + it * 256;
        int d = idx >> 5, c2 = idx & 31;
        int t = 2 * c2;
        uint32_t v = (uint32_t)tl[t][d] | ((uint32_t)tl[t + 1][d] << 16);
        *(uint32_t*)(g_vt + ((size_t)(bh * 64 + d)) * kT + t0 + t) = v;
    }
}

// ---------------------------------------------------------------------------
// Flash attention, fp16 mma, register Q/P, ldmatrix K/V frags.
// smem: K + V^T tiles double-buffered: 2 x 2 x 64 x 72 halves = 36,864 B.
// ---------------------------------------------------------------------------
constexpr int ATT_TILE_H = 64 * 72;
constexpr int ATT_STAGE_H = 2 * ATT_TILE_H;
constexpr int ATT_SMEM_BYTES = 2 * ATT_STAGE_H * 2;    // 36864

__global__ __launch_bounds__(128)
void attn_h_kernel()
{
    extern __shared__ __half smh[];

    const int qt = blockIdx.x;
    const int bh = blockIdx.y;
    const int b  = bh >> 4, h = bh & 15;
    const int tid = threadIdx.x, lane = tid & 31, warp = tid >> 5;
    const int g = lane >> 2, tg = lane & 3;
    const int m0 = warp * 32;

    const __half* Qg = g_qh + ((size_t)bh * kT + qt * 128) * kDH;
    const __half* Kg = g_kh + (size_t)bh * kT * kDH;
    const __half* Vt = g_vt + (size_t)bh * 64 * kT;

    // ldmatrix per-lane offsets for K/V B-frag tiles (row stride 72 halves)
    const int rowL = (lane & 7) + ((lane >> 4) << 3);
    const int kL   = ((lane >> 3) & 1) << 3;
    const uint32_t smbase = smem_u32(smh);
    const uint32_t lOff = (uint32_t)(rowL * 72 + kL) * 2;

    // Q fragments in registers
    uint32_t qf[4][2][4];
    #pragma unroll
    for (int kk = 0; kk < 4; kk++)
        #pragma unroll
        for (int mt = 0; mt < 2; mt++) {
            int r0 = m0 + mt * 16 + g;
            int k = kk * 16 + 2 * tg;
            qf[kk][mt][0] = *(const uint32_t*)(Qg + (size_t)r0 * 64 + k);
            qf[kk][mt][1] = *(const uint32_t*)(Qg + (size_t)(r0 + 8) * 64 + k);
            qf[kk][mt][2] = *(const uint32_t*)(Qg + (size_t)r0 * 64 + k + 8);
            qf[kk][mt][3] = *(const uint32_t*)(Qg + (size_t)(r0 + 8) * 64 + k + 8);
        }

    float o[2][8][4];
    #pragma unroll
    for (int mt = 0; mt < 2; mt++)
        #pragma unroll
        for (int nt = 0; nt < 8; nt++)
            #pragma unroll
            for (int e = 0; e < 4; e++) o[mt][nt][e] = 0.f;
    float mrow[4] = {-1e30f, -1e30f, -1e30f, -1e30f};
    float lrow[4] = {0.f, 0.f, 0.f, 0.f};

    const int nkt = 2 * qt + 2;

    auto load_stage = [&](int s, int kt) {
        __half* sK = smh + s * ATT_STAGE_H;
        __half* sV = sK + ATT_TILE_H;
        int bt0 = kt * 64;
        #pragma unroll
        for (int u = 0; u < 4; u++) {
            int idx = tid + u * 128;
            int r = idx >> 3, c16 = idx & 7;
            cpa16(sK + r * 72 + c16 * 8, Kg + ((size_t)(bt0 + r)) * 64 + c16 * 8);
        }
        #pragma unroll
        for (int u = 0; u < 4; u++) {
            int idx = tid + u * 128;
            int r = idx >> 3, c16 = idx & 7;
            cpa16(sV + r * 72 + c16 * 8, Vt + (size_t)r * kT + bt0 + c16 * 8);
        }
    };

    load_stage(0, 0);
    cpa_commit();

    for (int kt = 0; kt < nkt; kt++) {
        __syncthreads();
        if (kt + 1 < nkt) {
            load_stage((kt + 1) & 1, kt + 1);
            cpa_commit();
            asm volatile("cp.async.wait_group 1;\n");
        } else {
            asm volatile("cp.async.wait_group 0;\n");
        }
        __syncthreads();
        const uint32_t kAddr = smbase + (uint32_t)((kt & 1) * ATT_STAGE_H) * 2 + lOff;
        const uint32_t vAddr = kAddr + (uint32_t)ATT_TILE_H * 2;

        // S = Q @ K^T
        float s[2][8][4];
        #pragma unroll
        for (int mt = 0; mt < 2; mt++)
            #pragma unroll
            for (int nt = 0; nt < 8; nt++)
                #pragma unroll
                for (int e = 0; e < 4; e++) s[mt][nt][e] = 0.f;

        #pragma unroll
        for (int kk = 0; kk < 4; kk++) {
            uint32_t bq[4][4];
            #pragma unroll
            for (int np = 0; np < 4; np++)
                ldsm4(bq[np][0], bq[np][1], bq[np][2], bq[np][3],
                      kAddr + (uint32_t)(np * 16 * 72 + kk * 16) * 2);
            #pragma unroll
            for (int nt = 0; nt < 8; nt++) {
                uint32_t b0 = bq[nt >> 1][(nt & 1) * 2];
                uint32_t b1 = bq[nt >> 1][(nt & 1) * 2 + 1];
                #pragma unroll
                for (int mt = 0; mt < 2; mt++)
                    mma16(s[mt][nt][0], s[mt][nt][1], s[mt][nt][2], s[mt][nt][3],
                          qf[kk][mt][0], qf[kk][mt][1], qf[kk][mt][2], qf[kk][mt][3],
                          b0, b1);
            }
        }

        // causal mask
        if (kt >= 2 * qt) {
            int colbase = kt * 64;
            #pragma unroll
            for (int mt = 0; mt < 2; mt++) {
                int row = qt * 128 + m0 + mt * 16 + g;
                #pragma unroll
                for (int nt = 0; nt < 8; nt++) {
                    int col = colbase + nt * 8 + 2 * tg;
                    if (col > row)         s[mt][nt][0] = -1e30f;
                    if (col + 1 > row)     s[mt][nt][1] = -1e30f;
                    if (col > row + 8)     s[mt][nt][2] = -1e30f;
                    if (col + 1 > row + 8) s[mt][nt][3] = -1e30f;
                }
            }
        }

        // online softmax
        uint32_t p2[2][8][2];
        #pragma unroll
        for (int mt = 0; mt < 2; mt++) {
            float vm0 = -1e30f, vm1 = -1e30f;
            #pragma unroll
            for (int nt = 0; nt < 8; nt++) {
                vm0 = fmaxf(vm0, fmaxf(s[mt][nt][0], s[mt][nt][1]));
                vm1 = fmaxf(vm1, fmaxf(s[mt][nt][2], s[mt][nt][3]));
            }
            vm0 = fmaxf(vm0, __shfl_xor_sync(0xffffffffu, vm0, 1));
            vm0 = fmaxf(vm0, __shfl_xor_sync(0xffffffffu, vm0, 2));
            vm1 = fmaxf(vm1, __shfl_xor_sync(0xffffffffu, vm1, 1));
            vm1 = fmaxf(vm1, __shfl_xor_sync(0xffffffffu, vm1, 2));
            int i0 = mt * 2, i1 = mt * 2 + 1;
            float mn0 = fmaxf(mrow[i0], vm0), mn1 = fmaxf(mrow[i1], vm1);
            float c0 = __expf(mrow[i0] - mn0), c1 = __expf(mrow[i1] - mn1);
            mrow[i0] = mn0; mrow[i1] = mn1;
            float sum0 = 0.f, sum1 = 0.f;
            #pragma unroll
            for (int nt = 0; nt < 8; nt++) {
                float e0 = __expf(s[mt][nt][0] - mn0);
                float e1 = __expf(s[mt][nt][1] - mn0);
                float e2 = __expf(s[mt][nt][2] - mn1);
                float e3 = __expf(s[mt][nt][3] - mn1);
                sum0 += e0 + e1; sum1 += e2 + e3;
                p2[mt][nt][0] = packh2(e0, e1);
                p2[mt][nt][1] = packh2(e2, e3);
            }
            sum0 += __shfl_xor_sync(0xffffffffu, sum0, 1);
            sum0 += __shfl_xor_sync(0xffffffffu, sum0, 2);
            sum1 += __shfl_xor_sync(0xffffffffu, sum1, 1);
            sum1 += __shfl_xor_sync(0xffffffffu, sum1, 2);
            lrow[i0] = lrow[i0] * c0 + sum0;
            lrow[i1] = lrow[i1] * c1 + sum1;
            #pragma unroll
            for (int nt = 0; nt < 8; nt++) {
                o[mt][nt][0] *= c0; o[mt][nt][1] *= c0;
                o[mt][nt][2] *= c1; o[mt][nt][3] *= c1;
            }
        }

        // O += P @ V
        #pragma unroll
        for (int kk = 0; kk < 4; kk++) {
            int nt0 = kk * 2;
            uint32_t bq[4][4];
            #pragma unroll
            for (int np = 0; np < 4; np++)
                ldsm4(bq[np][0], bq[np][1], bq[np][2], bq[np][3],
                      vAddr + (uint32_t)(np * 16 * 72 + kk * 16) * 2);
            #pragma unroll
            for (int nt = 0; nt < 8; nt++) {
                uint32_t b0 = bq[nt >> 1][(nt & 1) * 2];
                uint32_t b1 = bq[nt >> 1][(nt & 1) * 2 + 1];
                #pragma unroll
                for (int mt = 0; mt < 2; mt++)
                    mma16(o[mt][nt][0], o[mt][nt][1], o[mt][nt][2], o[mt][nt][3],
                          p2[mt][nt0][0], p2[mt][nt0][1],
                          p2[mt][nt0 + 1][0], p2[mt][nt0 + 1][1],
                          b0, b1);
            }
        }
    }

    // epilogue: normalize, write fp16 [bt][h*64+d]
    #pragma unroll
    for (int mt = 0; mt < 2; mt++) {
        int r = m0 + mt * 16 + g;
        int grow = qt * 128 + r;
        float inv0 = 1.f / lrow[mt * 2];
        float inv1 = 1.f / lrow[mt * 2 + 1];
        #pragma unroll
        for (int nt = 0; nt < 8; nt++) {
            int c = h * 64 + nt * 8 + 2 * tg;
            size_t base0 = ((size_t)(b * kT) + grow) * kD + c;
            size_t base1 = ((size_t)(b * kT) + grow + 8) * kD + c;
            *(uint32_t*)&g_atth[base0] = packh2(o[mt][nt][0] * inv0, o[mt][nt][1] * inv0);
            *(uint32_t*)&g_atth[base1] = packh2(o[mt][nt][2] * inv1, o[mt][nt][3] * inv1);
        }
    }
}

// ---------------------------------------------------------------------------
extern "C" void kernel_launch(void* const* d_in, const int* in_sizes, int n_in,
                              void* d_out, int out_size)
{
    const float* x    = (const float*)d_in[0];
    const float* Wqkv = (const float*)d_in[1];
    const float* Wout = (const float*)d_in[2];
    float* out        = (float*)d_out;

    static bool attr_set = false;
    if (!attr_set) {
        cudaFuncSetAttribute(gemm_h_kernel,
                             cudaFuncAttributeMaxDynamicSharedMemorySize, GH_SMEM_BYTES);
        cudaFuncSetAttribute(attn_h_kernel,
                             cudaFuncAttributeMaxDynamicSharedMemorySize, ATT_SMEM_BYTES);
        attr_set = true;
    }

    __half* d_xh;    cudaGetSymbolAddress((void**)&d_xh, g_xh);
    __half* d_wqkvt; cudaGetSymbolAddress((void**)&d_wqkvt, g_wqkvt);
    __half* d_woutt; cudaGetSymbolAddress((void**)&d_woutt, g_woutt);
    __half* d_atth;  cudaGetSymbolAddress((void**)&d_atth, g_atth);
    float*  d_qkv;   cudaGetSymbolAddress((void**)&d_qkv, g_qkv);

    dim3 blk(256);

    // 0) convert inputs
    int nx = kBT * kD / 4;
    round_half_kernel<<<(nx + 255) / 256, blk>>>(x, (__half2*)d_xh, nx);
    round_transpose_kernel<<<dim3(kQKVN / 32, kD / 32), blk>>>(Wqkv, d_wqkvt, kD, kQKVN);
    round_transpose_kernel<<<dim3(kD / 32, kD / 32), blk>>>(Wout, d_woutt, kD, kD);

    // 1) QKV projection (fp16 mma + ldmatrix)
    gemm_h_kernel<<<dim3(kQKVN / 128, kBT / 128), blk, GH_SMEM_BYTES>>>(
        d_xh, d_wqkvt, d_qkv, kBT, kQKVN, kD);

    // 2) RoPE + head split (fp16 out, Q pre-scaled)
    int rope_threads = kBT * kH * 32;
    rope_kernel<<<(rope_threads + 255) / 256, blk>>>();

    // 2b) V transpose
    vtrans_kernel<<<dim3(kT / 64, kB * kH), blk>>>();

    // 3) causal flash attention (fp16 mma, register Q/P, ldmatrix K/V)
    attn_h_kernel<<<dim3(kT / 128, kB * kH), dim3(128), ATT_SMEM_BYTES>>>();

    // 4) output projection (fp16 mma + ldmatrix)
    gemm_h_kernel<<<dim3(kD / 128, kBT / 128), blk, GH_SMEM_BYTES>>>(
        d_atth, d_woutt, out, kBT, kD, kD);
}

// round 10
// speedup vs baseline: 15.5009x; 1.0756x over previous
#include <cuda_runtime.h>
#include <cuda_fp16.h>
#include <math.h>
#include <stdint.h>

// Problem dims
constexpr int kB  = 4;
constexpr int kT  = 2048;
constexpr int kD  = 1024;
constexpr int kH  = 16;
constexpr int kDH = 64;
constexpr int kBT = kB * kT;           // 8192
constexpr int kQKVN = 3 * kD;          // 3072

// Scratch
__device__ float  g_qkv[(size_t)kBT * kQKVN];      // 96 MB (gemm1 out, fp32)
__device__ __half g_xh[(size_t)kBT * kD];          // x in fp16
__device__ __half g_wqkvt[(size_t)kQKVN * kD];     // Wqkv^T fp16 [3072][1024]
__device__ __half g_woutt[(size_t)kD * kD];        // Wout^T fp16
__device__ __half g_qh[(size_t)kBT * kD];          // [bh][t][64], scaled 1/8
__device__ __half g_kh[(size_t)kBT * kD];
__device__ __half g_vh[(size_t)kBT * kD];          // [bh][t][64]
__device__ __half g_vt[(size_t)kBT * kD];          // [bh][64][kT] (V transposed)
__device__ __half g_atth[(size_t)kBT * kD];        // [bt][h*64+d]

// ---------------------------------------------------------------------------
__device__ __forceinline__ uint32_t packh2(float a, float b) {
    __half2 h = __floats2half2_rn(a, b);
    return *reinterpret_cast<uint32_t*>(&h);
}
__device__ __forceinline__ uint32_t smem_u32(const void* p) {
    return (uint32_t)__cvta_generic_to_shared(p);
}

__device__ __forceinline__ void mma16(float& d0, float& d1, float& d2, float& d3,
                                      uint32_t a0, uint32_t a1, uint32_t a2, uint32_t a3,
                                      uint32_t b0, uint32_t b1) {
    asm volatile(
        "mma.sync.aligned.m16n8k16.row.col.f32.f16.f16.f32 "
        "{%0,%1,%2,%3}, {%4,%5,%6,%7}, {%8,%9}, {%0,%1,%2,%3};\n"
        : "+f"(d0), "+f"(d1), "+f"(d2), "+f"(d3)
        : "r"(a0), "r"(a1), "r"(a2), "r"(a3), "r"(b0), "r"(b1));
}

__device__ __forceinline__ void ldsm4(uint32_t& r0, uint32_t& r1, uint32_t& r2,
                                      uint32_t& r3, uint32_t a) {
    asm volatile("ldmatrix.sync.aligned.m8n8.x4.shared.b16 {%0,%1,%2,%3}, [%4];"
        : "=r"(r0), "=r"(r1), "=r"(r2), "=r"(r3) : "r"(a));
}

__device__ __forceinline__ void cpa16(void* s, const void* g) {
    uint32_t sa = (uint32_t)__cvta_generic_to_shared(s);
    asm volatile("cp.async.cg.shared.global [%0], [%1], 16;\n" :: "r"(sa), "l"(g));
}
__device__ __forceinline__ void cpa_commit() {
    asm volatile("cp.async.commit_group;\n");
}

// ---------------------------------------------------------------------------
__global__ __launch_bounds__(256)
void round_half_kernel(const float* __restrict__ in, __half2* __restrict__ out, int n4)
{
    int i = blockIdx.x * blockDim.x + threadIdx.x;
    if (i >= n4) return;
    float4 v = ((const float4*)in)[i];
    out[2 * i]     = __floats2half2_rn(v.x, v.y);
    out[2 * i + 1] = __floats2half2_rn(v.z, v.w);
}

// W [K][N] float -> W^T [N][K] fp16
__global__ __launch_bounds__(256)
void round_transpose_kernel(const float* __restrict__ in, __half* __restrict__ out,
                            int K, int N)
{
    __shared__ float tile[32][33];
    int k0 = blockIdx.y * 32, n0 = blockIdx.x * 32;
    int tx = threadIdx.x & 31, ty = threadIdx.x >> 5;   // 32 x 8
    #pragma unroll
    for (int r = 0; r < 32; r += 8)
        tile[ty + r][tx] = in[(size_t)(k0 + ty + r) * N + n0 + tx];
    __syncthreads();
    #pragma unroll
    for (int r = 0; r < 32; r += 8)
        out[(size_t)(n0 + ty + r) * K + k0 + tx] = __float2half_rn(tile[tx][ty + r]);
}

// ---------------------------------------------------------------------------
// fp16 GEMM, ldmatrix frags, BK=64 (4 k16-slices per sync). CTA 128x128,
// 8 warps (2x4), warp tile 64x32, 3-stage cp.async pipeline.
// smem: 3 x (A[128][72] + B[128][72]) halves = 110,592 B -> 2 CTAs/SM.
// ---------------------------------------------------------------------------
constexpr int GH_TILE_H = 128 * 72;                    // 9216 halves
constexpr int GH_STAGE_H = 2 * GH_TILE_H;              // 18432
constexpr int GH_SMEM_BYTES = 3 * GH_STAGE_H * 2;      // 110592

__global__ __launch_bounds__(256, 2)
void gemm_h_kernel(const __half* __restrict__ A, const __half* __restrict__ Bt,
                   float* __restrict__ C, int M, int N, int K)
{
    extern __shared__ __half smh[];

    const int tid  = threadIdx.x;
    const int lane = tid & 31, warp = tid >> 5;
    const int wm = (warp >> 2) * 64, wn = (warp & 3) * 32;
    const int g = lane >> 2, tg = lane & 3;
    const int brow = blockIdx.y * 128, bcol = blockIdx.x * 128;

    // ldmatrix per-lane row/k offsets (row stride 72 halves)
    const int rowA = wm + (lane & 15);
    const int kA   = (lane >> 4) << 3;
    const int rowB = wn + (lane & 7) + ((lane >> 4) << 3);
    const int kBo  = ((lane >> 3) & 1) << 3;

    const uint32_t smbase = smem_u32(smh);
    const uint32_t aOff = (uint32_t)(rowA * 72 + kA) * 2;
    const uint32_t bOff = (uint32_t)GH_TILE_H * 2 + (uint32_t)(rowB * 72 + kBo) * 2;

    float acc[4][4][4];
    #pragma unroll
    for (int a = 0; a < 4; a++)
        #pragma unroll
        for (int b = 0; b < 4; b++)
            #pragma unroll
            for (int c = 0; c < 4; c++) acc[a][b][c] = 0.f;

    const int iters = K >> 6;   // BK = 64

    auto load_stage = [&](int s, int k0) {
        __half* As = smh + s * GH_STAGE_H;
        __half* Bs = As + GH_TILE_H;
        #pragma unroll
        for (int u = 0; u < 4; u++) {          // A: 128 rows x 8 cp16
            int idx = tid + u * 256;
            int r = idx >> 3, c16 = idx & 7;
            cpa16(As + r * 72 + c16 * 8, A + (size_t)(brow + r) * K + k0 + c16 * 8);
        }
        #pragma unroll
        for (int u = 0; u < 4; u++) {          // B: 128 n-rows x 8 cp16
            int idx = tid + u * 256;
            int r = idx >> 3, c16 = idx & 7;
            cpa16(Bs + r * 72 + c16 * 8, Bt + (size_t)(bcol + r) * K + k0 + c16 * 8);
        }
    };

    load_stage(0, 0);  cpa_commit();
    load_stage(1, 64); cpa_commit();

    for (int it = 0; it < iters; it++) {
        if (it + 1 < iters) asm volatile("cp.async.wait_group 1;\n");
        else                asm volatile("cp.async.wait_group 0;\n");
        __syncthreads();
        if (it + 2 < iters) {
            load_stage((it + 2) % 3, (it + 2) << 6);
            cpa_commit();
        }
        const uint32_t stg = smbase + (uint32_t)((it % 3) * GH_STAGE_H) * 2;
        const uint32_t aAddr = stg + aOff;
        const uint32_t bAddr = stg + bOff;

        #pragma unroll
        for (int ks = 0; ks < 64; ks += 16) {
            uint32_t a[4][4], bq[2][4];
            #pragma unroll
            for (int mt = 0; mt < 4; mt++)
                ldsm4(a[mt][0], a[mt][1], a[mt][2], a[mt][3],
                      aAddr + (uint32_t)(mt * 16 * 72 + ks) * 2);
            #pragma unroll
            for (int np = 0; np < 2; np++)
                ldsm4(bq[np][0], bq[np][1], bq[np][2], bq[np][3],
                      bAddr + (uint32_t)(np * 16 * 72 + ks) * 2);
            #pragma unroll
            for (int nt = 0; nt < 4; nt++) {
                uint32_t b0 = bq[nt >> 1][(nt & 1) * 2];
                uint32_t b1 = bq[nt >> 1][(nt & 1) * 2 + 1];
                #pragma unroll
                for (int mt = 0; mt < 4; mt++)
                    mma16(acc[mt][nt][0], acc[mt][nt][1], acc[mt][nt][2], acc[mt][nt][3],
                          a[mt][0], a[mt][1], a[mt][2], a[mt][3], b0, b1);
            }
        }
    }

    #pragma unroll
    for (int mt = 0; mt < 4; mt++) {
        #pragma unroll
        for (int nt = 0; nt < 4; nt++) {
            int r0 = brow + wm + mt * 16 + g;
            int c0 = bcol + wn + nt * 8 + 2 * tg;
            *(float2*)&C[(size_t)r0 * N + c0]       = make_float2(acc[mt][nt][0], acc[mt][nt][1]);
            *(float2*)&C[(size_t)(r0 + 8) * N + c0] = make_float2(acc[mt][nt][2], acc[mt][nt][3]);
        }
    }
}

// ---------------------------------------------------------------------------
// RoPE + split/transpose; outputs fp16; folds 1/8 softmax scale into Q.
// ---------------------------------------------------------------------------
__global__ __launch_bounds__(256)
void rope_kernel()
{
    int idx = blockIdx.x * blockDim.x + threadIdx.x;
    if (idx >= kBT * kH * 32) return;
    int i  = idx & 31;
    int h  = (idx >> 5) & (kH - 1);
    int bt = idx >> 9;
    int t  = bt & (kT - 1);
    int b  = bt >> 11;

    float inv_freq = expf(-((float)(2 * i) / 64.0f) * 9.210340371976184f);
    float ang = (float)t * inv_freq;
    float s, c;
    sincosf(ang, &s, &c);

    size_t src = (size_t)bt * kQKVN + h * kDH + i;
    float q1 = g_qkv[src],        q2 = g_qkv[src + 32];
    float k1 = g_qkv[src + 1024], k2 = g_qkv[src + 1056];
    float v1 = g_qkv[src + 2048], v2 = g_qkv[src + 2080];

    size_t dst = ((size_t)(b * kH + h) * kT + t) * kDH + i;
    g_qh[dst]      = __float2half_rn(0.125f * (q1 * c - q2 * s));
    g_qh[dst + 32] = __float2half_rn(0.125f * (q2 * c + q1 * s));
    g_kh[dst]      = __float2half_rn(k1 * c - k2 * s);
    g_kh[dst + 32] = __float2half_rn(k2 * c + k1 * s);
    g_vh[dst]      = __float2half_rn(v1);
    g_vh[dst + 32] = __float2half_rn(v2);
}

// V [bh][t][64] -> Vt [bh][64][kT]
__global__ __launch_bounds__(256)
void vtrans_kernel()
{
    __shared__ uint16_t tl[64][66];
    int t0 = blockIdx.x * 64;
    int bh = blockIdx.y;
    const uint32_t* src = (const uint32_t*)(g_vh + ((size_t)bh * kT + t0) * 64);
    #pragma unroll
    for (int it = 0; it < 8; it++) {
        int idx = threadIdx.x + it * 256;
        int r = idx >> 5, c2 = idx & 31;
        uint32_t v = src[r * 32 + c2];
        tl[r][2 * c2]     = (uint16_t)(v & 0xFFFF);
        tl[r][2 * c2 + 1] = (uint16_t)(v >> 16);
    }
    __syncthreads();
    #pragma unroll
    for (int it = 0; it < 8; it++) {
        int idx = threadIdx.x + it * 256;
        int d = idx >> 5, c2 = idx & 31;
        int t = 2 * c2;
        uint32_t v = (uint32_t)tl[t][d] | ((uint32_t)tl[t + 1][d] << 16);
        *(uint32_t*)(g_vt + ((size_t)(bh * 64 + d)) * kT + t0 + t) = v;
    }
}

// ---------------------------------------------------------------------------
// Flash attention, fp16 mma, register Q/P, ldmatrix K/V frags.
// smem: K + V^T tiles double-buffered: 2 x 2 x 64 x 72 halves = 36,864 B.
// ---------------------------------------------------------------------------
constexpr int ATT_TILE_H = 64 * 72;
constexpr int ATT_STAGE_H = 2 * ATT_TILE_H;
constexpr int ATT_SMEM_BYTES = 2 * ATT_STAGE_H * 2;    // 36864

__global__ __launch_bounds__(128)
void attn_h_kernel()
{
    extern __shared__ __half smh[];

    const int qt = blockIdx.x;
    const int bh = blockIdx.y;
    const int b  = bh >> 4, h = bh & 15;
    const int tid = threadIdx.x, lane = tid & 31, warp = tid >> 5;
    const int g = lane >> 2, tg = lane & 3;
    const int m0 = warp * 32;

    const __half* Qg = g_qh + ((size_t)bh * kT + qt * 128) * kDH;
    const __half* Kg = g_kh + (size_t)bh * kT * kDH;
    const __half* Vt = g_vt + (size_t)bh * 64 * kT;

    const int rowL = (lane & 7) + ((lane >> 4) << 3);
    const int kL   = ((lane >> 3) & 1) << 3;
    const uint32_t smbase = smem_u32(smh);
    const uint32_t lOff = (uint32_t)(rowL * 72 + kL) * 2;

    // Q fragments in registers
    uint32_t qf[4][2][4];
    #pragma unroll
    for (int kk = 0; kk < 4; kk++)
        #pragma unroll
        for (int mt = 0; mt < 2; mt++) {
            int r0 = m0 + mt * 16 + g;
            int k = kk * 16 + 2 * tg;
            qf[kk][mt][0] = *(const uint32_t*)(Qg + (size_t)r0 * 64 + k);
            qf[kk][mt][1] = *(const uint32_t*)(Qg + (size_t)(r0 + 8) * 64 + k);
            qf[kk][mt][2] = *(const uint32_t*)(Qg + (size_t)r0 * 64 + k + 8);
            qf[kk][mt][3] = *(const uint32_t*)(Qg + (size_t)(r0 + 8) * 64 + k + 8);
        }

    float o[2][8][4];
    #pragma unroll
    for (int mt = 0; mt < 2; mt++)
        #pragma unroll
        for (int nt = 0; nt < 8; nt++)
            #pragma unroll
            for (int e = 0; e < 4; e++) o[mt][nt][e] = 0.f;
    float mrow[4] = {-1e30f, -1e30f, -1e30f, -1e30f};
    float lrow[4] = {0.f, 0.f, 0.f, 0.f};

    const int nkt = 2 * qt + 2;

    auto load_stage = [&](int s, int kt) {
        __half* sK = smh + s * ATT_STAGE_H;
        __half* sV = sK + ATT_TILE_H;
        int bt0 = kt * 64;
        #pragma unroll
        for (int u = 0; u < 4; u++) {
            int idx = tid + u * 128;
            int r = idx >> 3, c16 = idx & 7;
            cpa16(sK + r * 72 + c16 * 8, Kg + ((size_t)(bt0 + r)) * 64 + c16 * 8);
        }
        #pragma unroll
        for (int u = 0; u < 4; u++) {
            int idx = tid + u * 128;
            int r = idx >> 3, c16 = idx & 7;
            cpa16(sV + r * 72 + c16 * 8, Vt + (size_t)r * kT + bt0 + c16 * 8);
        }
    };

    load_stage(0, 0);
    cpa_commit();

    for (int kt = 0; kt < nkt; kt++) {
        __syncthreads();
        if (kt + 1 < nkt) {
            load_stage((kt + 1) & 1, kt + 1);
            cpa_commit();
            asm volatile("cp.async.wait_group 1;\n");
        } else {
            asm volatile("cp.async.wait_group 0;\n");
        }
        __syncthreads();
        const uint32_t kAddr = smbase + (uint32_t)((kt & 1) * ATT_STAGE_H) * 2 + lOff;
        const uint32_t vAddr = kAddr + (uint32_t)ATT_TILE_H * 2;

        // S = Q @ K^T
        float s[2][8][4];
        #pragma unroll
        for (int mt = 0; mt < 2; mt++)
            #pragma unroll
            for (int nt = 0; nt < 8; nt++)
                #pragma unroll
                for (int e = 0; e < 4; e++) s[mt][nt][e] = 0.f;

        #pragma unroll
        for (int kk = 0; kk < 4; kk++) {
            uint32_t bq[4][4];
            #pragma unroll
            for (int np = 0; np < 4; np++)
                ldsm4(bq[np][0], bq[np][1], bq[np][2], bq[np][3],
                      kAddr + (uint32_t)(np * 16 * 72 + kk * 16) * 2);
            #pragma unroll
            for (int nt = 0; nt < 8; nt++) {
                uint32_t b0 = bq[nt >> 1][(nt & 1) * 2];
                uint32_t b1 = bq[nt >> 1][(nt & 1) * 2 + 1];
                #pragma unroll
                for (int mt = 0; mt < 2; mt++)
                    mma16(s[mt][nt][0], s[mt][nt][1], s[mt][nt][2], s[mt][nt][3],
                          qf[kk][mt][0], qf[kk][mt][1], qf[kk][mt][2], qf[kk][mt][3],
                          b0, b1);
            }
        }

        // causal mask
        if (kt >= 2 * qt) {
            int colbase = kt * 64;
            #pragma unroll
            for (int mt = 0; mt < 2; mt++) {
                int row = qt * 128 + m0 + mt * 16 + g;
                #pragma unroll
                for (int nt = 0; nt < 8; nt++) {
                    int col = colbase + nt * 8 + 2 * tg;
                    if (col > row)         s[mt][nt][0] = -1e30f;
                    if (col + 1 > row)     s[mt][nt][1] = -1e30f;
                    if (col > row + 8)     s[mt][nt][2] = -1e30f;
                    if (col + 1 > row + 8) s[mt][nt][3] = -1e30f;
                }
            }
        }

        // online softmax
        uint32_t p2[2][8][2];
        #pragma unroll
        for (int mt = 0; mt < 2; mt++) {
            float vm0 = -1e30f, vm1 = -1e30f;
            #pragma unroll
            for (int nt = 0; nt < 8; nt++) {
                vm0 = fmaxf(vm0, fmaxf(s[mt][nt][0], s[mt][nt][1]));
                vm1 = fmaxf(vm1, fmaxf(s[mt][nt][2], s[mt][nt][3]));
            }
            vm0 = fmaxf(vm0, __shfl_xor_sync(0xffffffffu, vm0, 1));
            vm0 = fmaxf(vm0, __shfl_xor_sync(0xffffffffu, vm0, 2));
            vm1 = fmaxf(vm1, __shfl_xor_sync(0xffffffffu, vm1, 1));
            vm1 = fmaxf(vm1, __shfl_xor_sync(0xffffffffu, vm1, 2));
            int i0 = mt * 2, i1 = mt * 2 + 1;
            float mn0 = fmaxf(mrow[i0], vm0), mn1 = fmaxf(mrow[i1], vm1);
            float c0 = __expf(mrow[i0] - mn0), c1 = __expf(mrow[i1] - mn1);
            mrow[i0] = mn0; mrow[i1] = mn1;
            float sum0 = 0.f, sum1 = 0.f;
            #pragma unroll
            for (int nt = 0; nt < 8; nt++) {
                float e0 = __expf(s[mt][nt][0] - mn0);
                float e1 = __expf(s[mt][nt][1] - mn0);
                float e2 = __expf(s[mt][nt][2] - mn1);
                float e3 = __expf(s[mt][nt][3] - mn1);
                sum0 += e0 + e1; sum1 += e2 + e3;
                p2[mt][nt][0] = packh2(e0, e1);
                p2[mt][nt][1] = packh2(e2, e3);
            }
            sum0 += __shfl_xor_sync(0xffffffffu, sum0, 1);
            sum0 += __shfl_xor_sync(0xffffffffu, sum0, 2);
            sum1 += __shfl_xor_sync(0xffffffffu, sum1, 1);
            sum1 += __shfl_xor_sync(0xffffffffu, sum1, 2);
            lrow[i0] = lrow[i0] * c0 + sum0;
            lrow[i1] = lrow[i1] * c1 + sum1;
            #pragma unroll
            for (int nt = 0; nt < 8; nt++) {
                o[mt][nt][0] *= c0; o[mt][nt][1] *= c0;
                o[mt][nt][2] *= c1; o[mt][nt][3] *= c1;
            }
        }

        // O += P @ V
        #pragma unroll
        for (int kk = 0; kk < 4; kk++) {
            int nt0 = kk * 2;
            uint32_t bq[4][4];
            #pragma unroll
            for (int np = 0; np < 4; np++)
                ldsm4(bq[np][0], bq[np][1], bq[np][2], bq[np][3],
                      vAddr + (uint32_t)(np * 16 * 72 + kk * 16) * 2);
            #pragma unroll
            for (int nt = 0; nt < 8; nt++) {
                uint32_t b0 = bq[nt >> 1][(nt & 1) * 2];
                uint32_t b1 = bq[nt >> 1][(nt & 1) * 2 + 1];
                #pragma unroll
                for (int mt = 0; mt < 2; mt++)
                    mma16(o[mt][nt][0], o[mt][nt][1], o[mt][nt][2], o[mt][nt][3],
                          p2[mt][nt0][0], p2[mt][nt0][1],
                          p2[mt][nt0 + 1][0], p2[mt][nt0 + 1][1],
                          b0, b1);
            }
        }
    }

    // epilogue: normalize, write fp16 [bt][h*64+d]
    #pragma unroll
    for (int mt = 0; mt < 2; mt++) {
        int r = m0 + mt * 16 + g;
        int grow = qt * 128 + r;
        float inv0 = 1.f / lrow[mt * 2];
        float inv1 = 1.f / lrow[mt * 2 + 1];
        #pragma unroll
        for (int nt = 0; nt < 8; nt++) {
            int c = h * 64 + nt * 8 + 2 * tg;
            size_t base0 = ((size_t)(b * kT) + grow) * kD + c;
            size_t base1 = ((size_t)(b * kT) + grow + 8) * kD + c;
            *(uint32_t*)&g_atth[base0] = packh2(o[mt][nt][0] * inv0, o[mt][nt][1] * inv0);
            *(uint32_t*)&g_atth[base1] = packh2(o[mt][nt][2] * inv1, o[mt][nt][3] * inv1);
        }
    }
}

// ---------------------------------------------------------------------------
extern "C" void kernel_launch(void* const* d_in, const int* in_sizes, int n_in,
                              void* d_out, int out_size)
{
    const float* x    = (const float*)d_in[0];
    const float* Wqkv = (const float*)d_in[1];
    const float* Wout = (const float*)d_in[2];
    float* out        = (float*)d_out;

    static bool attr_set = false;
    if (!attr_set) {
        cudaFuncSetAttribute(gemm_h_kernel,
                             cudaFuncAttributeMaxDynamicSharedMemorySize, GH_SMEM_BYTES);
        cudaFuncSetAttribute(attn_h_kernel,
                             cudaFuncAttributeMaxDynamicSharedMemorySize, ATT_SMEM_BYTES);
        attr_set = true;
    }

    __half* d_xh;    cudaGetSymbolAddress((void**)&d_xh, g_xh);
    __half* d_wqkvt; cudaGetSymbolAddress((void**)&d_wqkvt, g_wqkvt);
    __half* d_woutt; cudaGetSymbolAddress((void**)&d_woutt, g_woutt);
    __half* d_atth;  cudaGetSymbolAddress((void**)&d_atth, g_atth);
    float*  d_qkv;   cudaGetSymbolAddress((void**)&d_qkv, g_qkv);

    dim3 blk(256);

    // 0) convert inputs
    int nx = kBT * kD / 4;
    round_half_kernel<<<(nx + 255) / 256, blk>>>(x, (__half2*)d_xh, nx);
    round_transpose_kernel<<<dim3(kQKVN / 32, kD / 32), blk>>>(Wqkv, d_wqkvt, kD, kQKVN);
    round_transpose_kernel<<<dim3(kD / 32, kD / 32), blk>>>(Wout, d_woutt, kD, kD);

    // 1) QKV projection (fp16 mma + ldmatrix, BK=64)
    gemm_h_kernel<<<dim3(kQKVN / 128, kBT / 128), blk, GH_SMEM_BYTES>>>(
        d_xh, d_wqkvt, d_qkv, kBT, kQKVN, kD);

    // 2) RoPE + head split (fp16 out, Q pre-scaled)
    int rope_threads = kBT * kH * 32;
    rope_kernel<<<(rope_threads + 255) / 256, blk>>>();

    // 2b) V transpose
    vtrans_kernel<<<dim3(kT / 64, kB * kH), blk>>>();

    // 3) causal flash attention (fp16 mma, register Q/P, ldmatrix K/V)
    attn_h_kernel<<<dim3(kT / 128, kB * kH), dim3(128), ATT_SMEM_BYTES>>>();

    // 4) output projection (fp16 mma + ldmatrix, BK=64)
    gemm_h_kernel<<<dim3(kD / 128, kBT / 128), blk, GH_SMEM_BYTES>>>(
        d_atth, d_woutt, out, kBT, kD, kD);
}